// round 1
// baseline (speedup 1.0000x reference)
#include <cuda_runtime.h>
#include <math.h>

// Problem constants
#define NB 8
#define NT 8
#define BT 64          // NB*NT
#define NCODE 1024
#define Gd 128
#define CSd 64
#define TAd 256
#define SMAX 96        // cap on active codes per (b,t); mean ~52, +6 sigma safe
#define CMAX 64        // cap on adj CSR nnz per row; mean ~11

// ---------------- device scratch (static allocation only) ----------------
__device__ float d_EW1[NCODE * Gd];           // c_emb @ W1            512 KB
__device__ float2 d_csr[NCODE * CMAX];        // (col bitcast, val)    512 KB
__device__ int    d_ccnt[NCODE];
__device__ int    d_act[BT * SMAX];           // active code indices
__device__ int    d_scnt[BT];
__device__ unsigned char d_rank[BT * NCODE];  // code -> active rank (0xFF inactive)
__device__ float  d_psum;                     // sum(prior)
__device__ float  d_u[BT * SMAX * Gd];        // (adj @ h1) rows, active m only  3 MB
__device__ float  d_visit[BT * Gd];
__device__ float  d_zx[BT * 512];             // visit @ Wih + bih + bhh

// =========================================================================
// K1: setup — EW1, adj CSR, active lists, prior sum
// grid: 1089 blocks x 128 threads
// =========================================================================
__global__ void __launch_bounds__(128) k_setup(
    const float* __restrict__ adj, const float* __restrict__ code_x,
    const float* __restrict__ prior, const float* __restrict__ c_emb,
    const float* __restrict__ W1)
{
    int blk = blockIdx.x;
    int tid = threadIdx.x;

    if (blk < NCODE) {
        int n = blk;
        // ---- EW1 row n ----
        __shared__ float sc[CSd];
        if (tid < CSd) sc[tid] = c_emb[n * CSd + tid];
        __syncthreads();
        float acc = 0.f;
        int g = tid;
        #pragma unroll 16
        for (int j = 0; j < CSd; ++j) acc += sc[j] * W1[j * Gd + g];
        d_EW1[n * Gd + g] = acc;

        // ---- CSR row n (warp 0, order-preserving ballot compaction) ----
        if (tid < 32) {
            int lane = tid;
            int cnt = 0;
            for (int it = 0; it < 32; ++it) {
                int idx = it * 32 + lane;
                float v = adj[n * NCODE + idx];
                unsigned m = __ballot_sync(0xffffffffu, v != 0.f);
                if (v != 0.f) {
                    int pos = cnt + __popc(m & ((1u << lane) - 1u));
                    if (pos < CMAX)
                        d_csr[n * CMAX + pos] = make_float2(__int_as_float(idx), v);
                }
                cnt += __popc(m);
            }
            if (lane == 0) d_ccnt[n] = min(cnt, CMAX);
        }
    } else if (blk == NCODE) {
        // ---- prior sum ----
        __shared__ float sr[128];
        float s = 0.f;
        for (int i = tid; i < NCODE; i += 128) s += prior[i];
        sr[tid] = s; __syncthreads();
        for (int o = 64; o > 0; o >>= 1) {
            if (tid < o) sr[tid] += sr[tid + o];
            __syncthreads();
        }
        if (tid == 0) d_psum = sr[0];
    } else {
        // ---- active code gather per (b,t) ----
        int bt = blk - (NCODE + 1);
        if (tid < 32) {
            int lane = tid;
            for (int i = lane; i < NCODE; i += 32) d_rank[bt * NCODE + i] = 0xFF;
            __syncwarp();
            int cnt = 0;
            for (int it = 0; it < 32; ++it) {
                int idx = it * 32 + lane;
                float v = code_x[bt * NCODE + idx];
                unsigned m = __ballot_sync(0xffffffffu, v != 0.f);
                if (v != 0.f) {
                    int pos = cnt + __popc(m & ((1u << lane) - 1u));
                    if (pos < SMAX) {
                        d_act[bt * SMAX + pos] = idx;
                        d_rank[bt * NCODE + idx] = (unsigned char)pos;
                    }
                }
                cnt += __popc(m);
            }
            if (lane == 0) d_scnt[bt] = min(cnt, SMAX);
        }
    }
}

// =========================================================================
// K2: u[bt][m] = sum_{n in CSR(m)} adj[m,n] * relu( sum_{k in CSR(n) ∩ S} adj[n,k]*EW1[k] + b1 )
// (uses adj symmetry: column access == row access)
// grid: (24, 64) x 128 threads; one warp per active m
// =========================================================================
__global__ void __launch_bounds__(128) k_u(const float* __restrict__ b1)
{
    int bt = blockIdx.y;
    int warp = threadIdx.x >> 5;
    int lane = threadIdx.x & 31;
    int m = blockIdx.x * 4 + warp;
    int S = d_scnt[bt];
    if (m >= S) return;

    int am = d_act[bt * SMAX + m];
    const unsigned char* rk = d_rank + bt * NCODE;

    float bb[4], acc[4];
    #pragma unroll
    for (int q = 0; q < 4; ++q) { bb[q] = b1[lane + 32 * q]; acc[q] = 0.f; }

    int cm = d_ccnt[am];
    for (int e = 0; e < cm; ++e) {
        float2 cv = d_csr[am * CMAX + e];
        int n = __float_as_int(cv.x);
        float v = cv.y;
        float hv[4];
        #pragma unroll
        for (int q = 0; q < 4; ++q) hv[q] = bb[q];
        int cn = d_ccnt[n];
        for (int e2 = 0; e2 < cn; ++e2) {
            float2 cv2 = d_csr[n * CMAX + e2];
            int k = __float_as_int(cv2.x);
            if (rk[k] != 0xFF) {
                float v2 = cv2.y;
                const float* ew = d_EW1 + k * Gd;
                #pragma unroll
                for (int q = 0; q < 4; ++q) hv[q] += v2 * ew[lane + 32 * q];
            }
        }
        #pragma unroll
        for (int q = 0; q < 4; ++q) acc[q] += v * fmaxf(hv[q], 0.f);
    }
    #pragma unroll
    for (int q = 0; q < 4; ++q)
        d_u[(bt * SMAX + m) * Gd + lane + 32 * q] = acc[q];
}

// =========================================================================
// K3: per (b,t): co = u@W2+b2, prior-modulated LN + leaky residual,
//     masked code attention, visit vector, and zx = visit@Wih + bih + bhh.
// grid: 64 blocks x 256 threads, 96 KB dynamic smem
// =========================================================================
__global__ void __launch_bounds__(256) k_visit(
    const float* __restrict__ prior,
    const float* __restrict__ W2,  const float* __restrict__ b2,
    const float* __restrict__ Wp,  const float* __restrict__ bp,
    const float* __restrict__ lng, const float* __restrict__ lnb,
    const float* __restrict__ Wc,  const float* __restrict__ bc,
    const float* __restrict__ vc,
    const float* __restrict__ Wih, const float* __restrict__ bih,
    const float* __restrict__ bhh)
{
    extern __shared__ float dyn[];
    float* sU  = dyn;                 // [SMAX][Gd]
    float* sCo = dyn + SMAX * Gd;     // [SMAX][Gd]
    __shared__ int   sAct[SMAX];
    __shared__ float sPr[SMAX];
    __shared__ float sLogit[SMAX];
    __shared__ float sRed[8];
    __shared__ float sVisit[Gd];

    int bt  = blockIdx.x;
    int tid = threadIdx.x;
    int g    = tid & 127;
    int slot = tid >> 7;            // 0 or 1
    int warp = tid >> 5, lane = tid & 31;
    int S = d_scnt[bt];

    if (tid < SMAX) {
        int a = (tid < S) ? d_act[bt * SMAX + tid] : 0;
        sAct[tid] = a;
        sPr[tid]  = (tid < S) ? prior[a] / d_psum : 0.f;
    }
    for (int idx = tid; idx < SMAX * Gd; idx += 256) {
        int m = idx >> 7;
        sU[idx] = (m < S) ? d_u[bt * SMAX * Gd + idx] : 0.f;
    }
    __syncthreads();

    // ---- Phase B: co = u @ W2 + b2 ----
    int Sc = (S + 15) & ~15;
    float b2g = b2[g];
    for (int m0 = 0; m0 < Sc; m0 += 16) {
        float acc[8];
        #pragma unroll
        for (int i = 0; i < 8; ++i) acc[i] = 0.f;
        for (int j = 0; j < Gd; ++j) {
            float w = W2[j * Gd + g];
            #pragma unroll
            for (int i = 0; i < 8; ++i)
                acc[i] += sU[(m0 + slot + 2 * i) * Gd + j] * w;
        }
        #pragma unroll
        for (int i = 0; i < 8; ++i)
            sCo[(m0 + slot + 2 * i) * Gd + g] = acc[i] + b2g;
    }
    __syncthreads();

    // ---- Phase C: prior modulation + layernorm + leaky relu residual (warp per row) ----
    {
        float wpv[4], bpv[4], lg[4], lb[4];
        #pragma unroll
        for (int q = 0; q < 4; ++q) {
            int gg = lane + 32 * q;
            wpv[q] = Wp[gg]; bpv[q] = bp[gg]; lg[q] = lng[gg]; lb[q] = lnb[gg];
        }
        for (int m = warp; m < S; m += 8) {
            float p = sPr[m];
            float co[4], cw[4];
            float s = 0.f;
            #pragma unroll
            for (int q = 0; q < 4; ++q) {
                co[q] = sCo[m * Gd + lane + 32 * q];
                cw[q] = co[q] * (p * wpv[q] + bpv[q]);
                s += cw[q];
            }
            #pragma unroll
            for (int o = 16; o > 0; o >>= 1) s += __shfl_xor_sync(0xffffffffu, s, o);
            float mu = s * (1.f / 128.f);
            float vs = 0.f;
            #pragma unroll
            for (int q = 0; q < 4; ++q) { float d = cw[q] - mu; vs += d * d; }
            #pragma unroll
            for (int o = 16; o > 0; o >>= 1) vs += __shfl_xor_sync(0xffffffffu, vs, o);
            float inv = rsqrtf(vs * (1.f / 128.f) + 1e-5f);
            #pragma unroll
            for (int q = 0; q < 4; ++q) {
                float nv = (cw[q] - mu) * inv * lg[q] + lb[q];
                nv = (nv >= 0.f) ? nv : 0.01f * nv;
                sCo[m * Gd + lane + 32 * q] = co[q] + nv;
            }
        }
    }
    __syncthreads();

    // ---- Phase C2: attention logits logit[m] = vc . tanh(co[m]@Wc + bc) ----
    {
        float bcg = bc[g], vcg = vc[g];
        int Sc2 = (S + 1) & ~1;
        for (int m = slot; m < Sc2; m += 2) {
            float d = bcg;
            for (int j = 0; j < Gd; ++j) d += sCo[m * Gd + j] * Wc[j * Gd + g];
            float lt = tanhf(d) * vcg;
            #pragma unroll
            for (int o = 16; o > 0; o >>= 1) lt += __shfl_xor_sync(0xffffffffu, lt, o);
            if (lane == 0) sRed[warp] = lt;
            __syncthreads();
            if ((tid & 127) == 0 && m < S) {
                sLogit[m] = sRed[slot * 4] + sRed[slot * 4 + 1] +
                            sRed[slot * 4 + 2] + sRed[slot * 4 + 3];
            }
            __syncthreads();
        }
    }

    // ---- Phase D: softmax over active codes + visit ----
    if (tid < 32) {
        float mx = -3.0e38f;
        for (int m = tid; m < S; m += 32) mx = fmaxf(mx, sLogit[m]);
        #pragma unroll
        for (int o = 16; o > 0; o >>= 1) mx = fmaxf(mx, __shfl_xor_sync(0xffffffffu, mx, o));
        float se = 0.f;
        for (int m = tid; m < S; m += 32) {
            float e = expf(sLogit[m] - mx);
            sLogit[m] = e; se += e;
        }
        #pragma unroll
        for (int o = 16; o > 0; o >>= 1) se += __shfl_xor_sync(0xffffffffu, se, o);
        float inv = 1.f / se;
        for (int m = tid; m < S; m += 32) sLogit[m] *= inv;
    }
    __syncthreads();
    if (slot == 0) {
        float v = 0.f;
        for (int m = 0; m < S; ++m) v += sLogit[m] * sCo[m * Gd + g];
        sVisit[g] = v;
        d_visit[bt * Gd + g] = v;
    }
    __syncthreads();

    // ---- zx = visit @ Wih + bih + bhh (parallel part of LSTM gates) ----
    #pragma unroll
    for (int jh = 0; jh < 2; ++jh) {
        int j = jh * 256 + tid;
        float z = bih[j] + bhh[j];
        for (int k = 0; k < Gd; ++k) z += sVisit[k] * Wih[k * 512 + j];
        d_zx[bt * 512 + j] = z;
    }
}

// =========================================================================
// K4: LSTM recurrence + temporal attention + classifier. grid: 8 x 256
// =========================================================================
__global__ void __launch_bounds__(256) k_lstm(
    const float* __restrict__ Whh, const float* __restrict__ Wt,
    const float* __restrict__ btv, const float* __restrict__ vt,
    const float* __restrict__ Wcls, const float* __restrict__ bcls,
    float* __restrict__ out)
{
    __shared__ float sh[128], scst[128], shs[8 * 128], szp[2 * 512];
    __shared__ float sU8[8], sRed[8];

    int b = blockIdx.x, tid = threadIdx.x;
    int jj = tid & 127, kh = tid >> 7;
    int warp = tid >> 5, lane = tid & 31;

    if (tid < 128) { sh[tid] = 0.f; scst[tid] = 0.f; }
    __syncthreads();

    for (int t = 0; t < 8; ++t) {
        // partial z = h @ Whh over k half
        float4 z4 = make_float4(0.f, 0.f, 0.f, 0.f);
        const float* wp = Whh + jj * 4;
        for (int k = kh * 64; k < kh * 64 + 64; ++k) {
            float hv = sh[k];
            float4 w = *reinterpret_cast<const float4*>(wp + k * 512);
            z4.x += hv * w.x; z4.y += hv * w.y; z4.z += hv * w.z; z4.w += hv * w.w;
        }
        reinterpret_cast<float4*>(szp + kh * 512)[jj] = z4;
        __syncthreads();
        if (tid < 128) {
            const float* zx = d_zx + (b * 8 + t) * 512;
            float zi = zx[tid]       + szp[tid]       + szp[512 + tid];
            float zf = zx[tid + 128] + szp[tid + 128] + szp[512 + tid + 128];
            float zg = zx[tid + 256] + szp[tid + 256] + szp[512 + tid + 256];
            float zo = zx[tid + 384] + szp[tid + 384] + szp[512 + tid + 384];
            float iv = 1.f / (1.f + expf(-zi));
            float fv = 1.f / (1.f + expf(-zf));
            float gv = tanhf(zg);
            float ov = 1.f / (1.f + expf(-zo));
            float c = fv * scst[tid] + iv * gv;
            scst[tid] = c;
            float h = ov * tanhf(c);
            sh[tid] = h;
            shs[t * 128 + tid] = h;
        }
        __syncthreads();
    }

    // ---- temporal attention u[t] = vt . tanh(h_t @ Wt + bt) ----
    for (int t = 0; t < 8; ++t) {
        float a = btv[tid];
        for (int h = 0; h < 128; ++h) a += shs[t * 128 + h] * Wt[h * TAd + tid];
        a = tanhf(a) * vt[tid];
        #pragma unroll
        for (int o = 16; o > 0; o >>= 1) a += __shfl_xor_sync(0xffffffffu, a, o);
        if (lane == 0) sRed[warp] = a;
        __syncthreads();
        if (tid == 0) {
            float s = 0.f;
            #pragma unroll
            for (int w = 0; w < 8; ++w) s += sRed[w];
            sU8[t] = s;
        }
        __syncthreads();
    }
    if (tid == 0) {
        float mx = -3.0e38f;
        #pragma unroll
        for (int t = 0; t < 8; ++t) mx = fmaxf(mx, sU8[t]);
        float se = 0.f;
        #pragma unroll
        for (int t = 0; t < 8; ++t) { float e = expf(sU8[t] - mx); sU8[t] = e; se += e; }
        float inv = 1.f / se;
        #pragma unroll
        for (int t = 0; t < 8; ++t) sU8[t] *= inv;
    }
    __syncthreads();

    // ---- pooled @ Wcls + bcls ----
    float partial = 0.f;
    if (tid < 128) {
        float p = 0.f;
        #pragma unroll
        for (int t = 0; t < 8; ++t) p += sU8[t] * shs[t * 128 + tid];
        partial = p * Wcls[tid];
    }
    #pragma unroll
    for (int o = 16; o > 0; o >>= 1) partial += __shfl_xor_sync(0xffffffffu, partial, o);
    if (lane == 0) sRed[warp] = partial;
    __syncthreads();
    if (tid == 0) {
        float s = 0.f;
        #pragma unroll
        for (int w = 0; w < 8; ++w) s += sRed[w];
        out[b] = s + bcls[0];
    }
}

// =========================================================================
extern "C" void kernel_launch(void* const* d_in, const int* in_sizes, int n_in,
                              void* d_out, int out_size)
{
    const float* code_x = (const float*)d_in[0];
    // d_in[1] divided, d_in[2] neighbors, d_in[3] lens — unused by forward
    const float* prior  = (const float*)d_in[4];
    const float* adj    = (const float*)d_in[5];
    const float* c_emb  = (const float*)d_in[6];
    const float* W1     = (const float*)d_in[7];
    const float* b1     = (const float*)d_in[8];
    const float* W2     = (const float*)d_in[9];
    const float* b2     = (const float*)d_in[10];
    const float* Wp     = (const float*)d_in[11];
    const float* bp     = (const float*)d_in[12];
    const float* ln_g   = (const float*)d_in[13];
    const float* ln_b   = (const float*)d_in[14];
    const float* Wc     = (const float*)d_in[15];
    const float* bc     = (const float*)d_in[16];
    const float* vc     = (const float*)d_in[17];
    const float* Wt     = (const float*)d_in[18];
    const float* btv    = (const float*)d_in[19];
    const float* vt     = (const float*)d_in[20];
    const float* Wih    = (const float*)d_in[21];
    const float* Whh    = (const float*)d_in[22];
    const float* bih    = (const float*)d_in[23];
    const float* bhh    = (const float*)d_in[24];
    const float* Wcls   = (const float*)d_in[25];
    const float* bcls   = (const float*)d_in[26];

    cudaFuncSetAttribute(k_visit, cudaFuncAttributeMaxDynamicSharedMemorySize,
                         SMAX * Gd * 2 * (int)sizeof(float));

    k_setup<<<NCODE + 1 + BT, 128>>>(adj, code_x, prior, c_emb, W1);
    k_u<<<dim3(SMAX / 4, BT), 128>>>(b1);
    k_visit<<<BT, 256, SMAX * Gd * 2 * sizeof(float)>>>(
        prior, W2, b2, Wp, bp, ln_g, ln_b, Wc, bc, vc, Wih, bih, bhh);
    k_lstm<<<NB, 256>>>(Whh, Wt, btv, vt, Wcls, bcls, (float*)d_out);
}

// round 2
// speedup vs baseline: 1.5856x; 1.5856x over previous
#include <cuda_runtime.h>
#include <math.h>

// Problem constants
#define NB 8
#define NT 8
#define BT 64          // NB*NT
#define NCODE 1024
#define Gd 128
#define CSd 64
#define TAd 256
#define SMAX 96        // cap on active codes per (b,t)
#define CMAX 64        // cap on adj CSR nnz per row
#define HALF 48        // rows per kAC block (SMAX/2)

// ---------------- device scratch (static allocation only) ----------------
__device__ float d_EW1[NCODE * Gd];           // c_emb @ W1
__device__ float2 d_csr[NCODE * CMAX];        // (col bitcast, val)
__device__ int    d_ccnt[NCODE];
__device__ int    d_act[BT * SMAX];           // active code indices
__device__ int    d_scnt[BT];
__device__ unsigned char d_rank[BT * NCODE];  // code -> active rank (0xFF inactive)
__device__ float  d_psum;                     // sum(prior)
__device__ float  d_logit[BT * SMAX];
__device__ float  d_co[BT * SMAX * Gd];       // post-residual co rows (active only)
__device__ float  d_zx[BT * 512];             // visit @ Wih + bih + bhh

// =========================================================================
// K1: setup — EW1, adj CSR, active lists, prior sum
// =========================================================================
__global__ void __launch_bounds__(128) k_setup(
    const float* __restrict__ adj, const float* __restrict__ code_x,
    const float* __restrict__ prior, const float* __restrict__ c_emb,
    const float* __restrict__ W1)
{
    int blk = blockIdx.x;
    int tid = threadIdx.x;

    if (blk < NCODE) {
        int n = blk;
        __shared__ float sc[CSd];
        if (tid < CSd) sc[tid] = c_emb[n * CSd + tid];
        __syncthreads();
        float acc = 0.f;
        int g = tid;
        #pragma unroll 16
        for (int j = 0; j < CSd; ++j) acc += sc[j] * W1[j * Gd + g];
        d_EW1[n * Gd + g] = acc;

        if (tid < 32) {
            int lane = tid;
            int cnt = 0;
            for (int it = 0; it < 32; ++it) {
                int idx = it * 32 + lane;
                float v = adj[n * NCODE + idx];
                unsigned m = __ballot_sync(0xffffffffu, v != 0.f);
                if (v != 0.f) {
                    int pos = cnt + __popc(m & ((1u << lane) - 1u));
                    if (pos < CMAX)
                        d_csr[n * CMAX + pos] = make_float2(__int_as_float(idx), v);
                }
                cnt += __popc(m);
            }
            if (lane == 0) d_ccnt[n] = min(cnt, CMAX);
        }
    } else if (blk == NCODE) {
        __shared__ float sr[128];
        float s = 0.f;
        for (int i = tid; i < NCODE; i += 128) s += prior[i];
        sr[tid] = s; __syncthreads();
        for (int o = 64; o > 0; o >>= 1) {
            if (tid < o) sr[tid] += sr[tid + o];
            __syncthreads();
        }
        if (tid == 0) d_psum = sr[0];
    } else {
        int bt = blk - (NCODE + 1);
        if (tid < 32) {
            int lane = tid;
            for (int i = lane; i < NCODE; i += 32) d_rank[bt * NCODE + i] = 0xFF;
            __syncwarp();
            int cnt = 0;
            for (int it = 0; it < 32; ++it) {
                int idx = it * 32 + lane;
                float v = code_x[bt * NCODE + idx];
                unsigned m = __ballot_sync(0xffffffffu, v != 0.f);
                if (v != 0.f) {
                    int pos = cnt + __popc(m & ((1u << lane) - 1u));
                    if (pos < SMAX) {
                        d_act[bt * SMAX + pos] = idx;
                        d_rank[bt * NCODE + idx] = (unsigned char)pos;
                    }
                }
                cnt += __popc(m);
            }
            if (lane == 0) d_scnt[bt] = min(cnt, SMAX);
        }
    }
}

// =========================================================================
// K2: kAC — per (bt, row-half): u rows (sparse GCN), co=u@W2+b2, LN residual,
//     attention logits. grid (2, 64) x 512 threads, 48KB dyn smem.
// =========================================================================
__global__ void __launch_bounds__(512) kAC(
    const float* __restrict__ prior, const float* __restrict__ b1,
    const float* __restrict__ W2,  const float* __restrict__ b2,
    const float* __restrict__ Wp,  const float* __restrict__ bp,
    const float* __restrict__ lng, const float* __restrict__ lnb,
    const float* __restrict__ Wc,  const float* __restrict__ bc,
    const float* __restrict__ vc)
{
    extern __shared__ float dyn[];
    float* sU  = dyn;                // [HALF][Gd]
    float* sCo = dyn + HALF * Gd;    // [HALF][Gd]
    __shared__ unsigned char sRank[NCODE];
    __shared__ float sPr[HALF];
    __shared__ float sRedC[4][4][4]; // [slot][warpInSlot][i]

    int half = blockIdx.x, bt = blockIdx.y;
    int tid = threadIdx.x;
    int warp = tid >> 5, lane = tid & 31;
    int slot = tid >> 7, g = tid & 127;
    int wis  = warp & 3;             // warp within slot
    int S = d_scnt[bt];
    int base = half * HALF;
    int rows = min(S - base, HALF);
    if (rows <= 0) return;

    for (int i = tid; i < NCODE; i += 512) sRank[i] = d_rank[bt * NCODE + i];
    if (tid < HALF)
        sPr[tid] = (tid < rows) ? prior[d_act[bt * SMAX + base + tid]] / d_psum : 0.f;
    __syncthreads();

    // ---- Phase A: u rows (one warp per row) ----
    {
        float bb[4];
        #pragma unroll
        for (int q = 0; q < 4; ++q) bb[q] = b1[lane + 32 * q];
        for (int mi = warp; mi < rows; mi += 16) {
            int am = d_act[bt * SMAX + base + mi];
            float acc[4] = {0.f, 0.f, 0.f, 0.f};
            int cm = d_ccnt[am];
            for (int e = 0; e < cm; ++e) {
                float2 cv = d_csr[am * CMAX + e];
                int n = __float_as_int(cv.x);
                float v = cv.y;
                float hv[4];
                #pragma unroll
                for (int q = 0; q < 4; ++q) hv[q] = bb[q];
                int cn = d_ccnt[n];
                for (int e2 = 0; e2 < cn; ++e2) {
                    float2 cv2 = d_csr[n * CMAX + e2];
                    int k = __float_as_int(cv2.x);
                    if (sRank[k] != 0xFF) {
                        float v2 = cv2.y;
                        const float* ew = d_EW1 + k * Gd;
                        #pragma unroll
                        for (int q = 0; q < 4; ++q) hv[q] += v2 * ew[lane + 32 * q];
                    }
                }
                #pragma unroll
                for (int q = 0; q < 4; ++q) acc[q] += v * fmaxf(hv[q], 0.f);
            }
            #pragma unroll
            for (int q = 0; q < 4; ++q) sU[mi * Gd + lane + 32 * q] = acc[q];
        }
        // zero-pad to 16-row multiple
        int rowsC = (rows + 15) & ~15;
        for (int mi = rows + warp; mi < rowsC; mi += 16) {
            #pragma unroll
            for (int q = 0; q < 4; ++q) sU[mi * Gd + lane + 32 * q] = 0.f;
        }
    }
    __syncthreads();

    int rowsC = (rows + 15) & ~15;

    // ---- Phase B: co = u @ W2 + b2 ----
    {
        float b2g = b2[g];
        for (int m0 = 0; m0 < rowsC; m0 += 16) {
            float acc[4] = {0.f, 0.f, 0.f, 0.f};
            #pragma unroll 4
            for (int j = 0; j < Gd; ++j) {
                float w = W2[j * Gd + g];
                #pragma unroll
                for (int i = 0; i < 4; ++i)
                    acc[i] += sU[(m0 + slot + 4 * i) * Gd + j] * w;
            }
            #pragma unroll
            for (int i = 0; i < 4; ++i)
                sCo[(m0 + slot + 4 * i) * Gd + g] = acc[i] + b2g;
        }
    }
    __syncthreads();

    // ---- Phase C: prior modulation + LN + leaky relu residual (warp per row) ----
    {
        float wpv[4], bpv[4], lg[4], lb[4];
        #pragma unroll
        for (int q = 0; q < 4; ++q) {
            int gg = lane + 32 * q;
            wpv[q] = Wp[gg]; bpv[q] = bp[gg]; lg[q] = lng[gg]; lb[q] = lnb[gg];
        }
        for (int mi = warp; mi < rows; mi += 16) {
            float p = sPr[mi];
            float co[4], cw[4];
            float s = 0.f;
            #pragma unroll
            for (int q = 0; q < 4; ++q) {
                co[q] = sCo[mi * Gd + lane + 32 * q];
                cw[q] = co[q] * (p * wpv[q] + bpv[q]);
                s += cw[q];
            }
            #pragma unroll
            for (int o = 16; o > 0; o >>= 1) s += __shfl_xor_sync(0xffffffffu, s, o);
            float mu = s * (1.f / 128.f);
            float vs = 0.f;
            #pragma unroll
            for (int q = 0; q < 4; ++q) { float d = cw[q] - mu; vs += d * d; }
            #pragma unroll
            for (int o = 16; o > 0; o >>= 1) vs += __shfl_xor_sync(0xffffffffu, vs, o);
            float inv = rsqrtf(vs * (1.f / 128.f) + 1e-5f);
            #pragma unroll
            for (int q = 0; q < 4; ++q) {
                float nv = (cw[q] - mu) * inv * lg[q] + lb[q];
                nv = (nv >= 0.f) ? nv : 0.01f * nv;
                sCo[mi * Gd + lane + 32 * q] = co[q] + nv;
            }
        }
    }
    __syncthreads();

    // ---- Phase C2: logits = tanh(co@Wc + bc) @ vc ----
    {
        float bcg = bc[g], vcg = vc[g];
        for (int m0 = 0; m0 < rowsC; m0 += 16) {
            float acc[4] = {0.f, 0.f, 0.f, 0.f};
            #pragma unroll 4
            for (int j = 0; j < Gd; ++j) {
                float w = Wc[j * Gd + g];
                #pragma unroll
                for (int i = 0; i < 4; ++i)
                    acc[i] += sCo[(m0 + slot + 4 * i) * Gd + j] * w;
            }
            #pragma unroll
            for (int i = 0; i < 4; ++i) {
                float tv = tanhf(acc[i] + bcg) * vcg;
                #pragma unroll
                for (int o = 16; o > 0; o >>= 1)
                    tv += __shfl_xor_sync(0xffffffffu, tv, o);
                if (lane == 0) sRedC[slot][wis][i] = tv;
            }
            __syncthreads();
            if (tid < 16) {
                int s2 = tid & 3, i2 = tid >> 2;
                int row = m0 + s2 + 4 * i2;
                if (row < rows) {
                    d_logit[bt * SMAX + base + row] =
                        sRedC[s2][0][i2] + sRedC[s2][1][i2] +
                        sRedC[s2][2][i2] + sRedC[s2][3][i2];
                }
            }
            __syncthreads();
        }
    }

    // ---- write co rows ----
    for (int idx = tid; idx < rows * Gd; idx += 512)
        d_co[(bt * SMAX + base) * Gd + idx] = sCo[idx];
}

// =========================================================================
// K3: kD — softmax over active codes, visit vector, zx = visit@Wih+bih+bhh
// grid 64 x 256, 48KB dyn smem
// =========================================================================
__global__ void __launch_bounds__(256) kD(
    const float* __restrict__ Wih, const float* __restrict__ bih,
    const float* __restrict__ bhh)
{
    extern __shared__ float sCoD[];      // [SMAX][Gd]
    __shared__ float sAttn[SMAX];
    __shared__ float sVis[Gd];

    int bt = blockIdx.x, tid = threadIdx.x;
    int S = d_scnt[bt];

    for (int idx = tid; idx < S * Gd; idx += 256)
        sCoD[idx] = d_co[bt * SMAX * Gd + idx];

    if (tid < 32) {
        float mx = -3.0e38f;
        for (int m = tid; m < S; m += 32) {
            float l = d_logit[bt * SMAX + m];
            sAttn[m] = l;
            mx = fmaxf(mx, l);
        }
        #pragma unroll
        for (int o = 16; o > 0; o >>= 1)
            mx = fmaxf(mx, __shfl_xor_sync(0xffffffffu, mx, o));
        float se = 0.f;
        for (int m = tid; m < S; m += 32) {
            float e = expf(sAttn[m] - mx);
            sAttn[m] = e; se += e;
        }
        #pragma unroll
        for (int o = 16; o > 0; o >>= 1) se += __shfl_xor_sync(0xffffffffu, se, o);
        float inv = 1.f / se;
        for (int m = tid; m < S; m += 32) sAttn[m] *= inv;
    }
    __syncthreads();

    if (tid < Gd) {
        float v = 0.f;
        for (int m = 0; m < S; ++m) v += sAttn[m] * sCoD[m * Gd + tid];
        sVis[tid] = v;
    }
    __syncthreads();

    for (int j = tid; j < 512; j += 256) {
        float z = bih[j] + bhh[j];
        #pragma unroll 4
        for (int k = 0; k < Gd; ++k) z += sVis[k] * Wih[k * 512 + j];
        d_zx[bt * 512 + j] = z;
    }
}

// =========================================================================
// K4: LSTM recurrence + temporal attention + classifier.
// grid 8 x 1024, dyn smem = 128KB Whh cache + 16KB partials
// =========================================================================
__global__ void __launch_bounds__(1024) k_lstm(
    const float* __restrict__ Whh, const float* __restrict__ Wt,
    const float* __restrict__ btv, const float* __restrict__ vt,
    const float* __restrict__ Wcls, const float* __restrict__ bcls,
    float* __restrict__ out)
{
    extern __shared__ float dynl[];
    float* sWhh = dynl;               // [64][512]  (k < 64 slice of Whh)
    float* szp  = dynl + 64 * 512;    // [8][512]
    __shared__ float sh[128], scst[128], shs[8 * 128], sz[512];
    __shared__ float sU8[8], sRedT[8][8], sRedF[4];

    int b = blockIdx.x, tid = threadIdx.x;
    int jq = tid & 127, kh = tid >> 7;
    int warp = tid >> 5, lane = tid & 31;

    // preload first half of Whh into smem
    for (int idx = tid; idx < 64 * 512 / 4; idx += 1024)
        reinterpret_cast<float4*>(sWhh)[idx] =
            reinterpret_cast<const float4*>(Whh)[idx];
    if (tid < 128) { sh[tid] = 0.f; scst[tid] = 0.f; }
    __syncthreads();

    for (int t = 0; t < 8; ++t) {
        if (t > 0) {
            float4 z4 = make_float4(0.f, 0.f, 0.f, 0.f);
            if (kh < 4) {
                #pragma unroll
                for (int kk = 0; kk < 16; ++kk) {
                    int k = kh * 16 + kk;
                    float hv = sh[k];
                    float4 w = reinterpret_cast<const float4*>(sWhh)[k * 128 + jq];
                    z4.x += hv * w.x; z4.y += hv * w.y;
                    z4.z += hv * w.z; z4.w += hv * w.w;
                }
            } else {
                #pragma unroll
                for (int kk = 0; kk < 16; ++kk) {
                    int k = kh * 16 + kk;
                    float hv = sh[k];
                    float4 w = *reinterpret_cast<const float4*>(Whh + k * 512 + jq * 4);
                    z4.x += hv * w.x; z4.y += hv * w.y;
                    z4.z += hv * w.z; z4.w += hv * w.w;
                }
            }
            reinterpret_cast<float4*>(szp + kh * 512)[jq] = z4;
        }
        __syncthreads();
        if (tid < 512) {
            float z = d_zx[(b * 8 + t) * 512 + tid];
            if (t > 0) {
                #pragma unroll
                for (int q = 0; q < 8; ++q) z += szp[q * 512 + tid];
            }
            sz[tid] = z;
        }
        __syncthreads();
        if (tid < 128) {
            float zi = sz[tid], zf = sz[tid + 128], zg = sz[tid + 256], zo = sz[tid + 384];
            float iv = 1.f / (1.f + expf(-zi));
            float fv = 1.f / (1.f + expf(-zf));
            float gv = tanhf(zg);
            float ov = 1.f / (1.f + expf(-zo));
            float c = fv * scst[tid] + iv * gv;
            scst[tid] = c;
            float h = ov * tanhf(c);
            sh[tid] = h;
            shs[t * 128 + tid] = h;
        }
        __syncthreads();
    }

    // ---- temporal attention: parallel over (t, ta) ----
    #pragma unroll
    for (int rep = 0; rep < 2; ++rep) {
        int t = (tid >> 8) + rep * 4;
        int ta = tid & 255;
        float a = btv[ta];
        #pragma unroll 4
        for (int h = 0; h < 128; ++h) a += shs[t * 128 + h] * Wt[h * TAd + ta];
        a = tanhf(a) * vt[ta];
        #pragma unroll
        for (int o = 16; o > 0; o >>= 1) a += __shfl_xor_sync(0xffffffffu, a, o);
        if (lane == 0) sRedT[t][warp & 7] = a;
    }
    __syncthreads();
    if (tid < 8) {
        float s = 0.f;
        #pragma unroll
        for (int w = 0; w < 8; ++w) s += sRedT[tid][w];
        sU8[tid] = s;
    }
    __syncthreads();
    if (tid == 0) {
        float mx = -3.0e38f;
        #pragma unroll
        for (int t = 0; t < 8; ++t) mx = fmaxf(mx, sU8[t]);
        float se = 0.f;
        #pragma unroll
        for (int t = 0; t < 8; ++t) { float e = expf(sU8[t] - mx); sU8[t] = e; se += e; }
        float inv = 1.f / se;
        #pragma unroll
        for (int t = 0; t < 8; ++t) sU8[t] *= inv;
    }
    __syncthreads();

    float partial = 0.f;
    if (tid < 128) {
        float p = 0.f;
        #pragma unroll
        for (int t = 0; t < 8; ++t) p += sU8[t] * shs[t * 128 + tid];
        partial = p * Wcls[tid];
    }
    #pragma unroll
    for (int o = 16; o > 0; o >>= 1) partial += __shfl_xor_sync(0xffffffffu, partial, o);
    if (lane == 0 && warp < 4) sRedF[warp] = partial;
    __syncthreads();
    if (tid == 0) {
        out[b] = sRedF[0] + sRedF[1] + sRedF[2] + sRedF[3] + bcls[0];
    }
}

// =========================================================================
extern "C" void kernel_launch(void* const* d_in, const int* in_sizes, int n_in,
                              void* d_out, int out_size)
{
    const float* code_x = (const float*)d_in[0];
    // d_in[1] divided, d_in[2] neighbors, d_in[3] lens — unused by forward
    const float* prior  = (const float*)d_in[4];
    const float* adj    = (const float*)d_in[5];
    const float* c_emb  = (const float*)d_in[6];
    const float* W1     = (const float*)d_in[7];
    const float* b1     = (const float*)d_in[8];
    const float* W2     = (const float*)d_in[9];
    const float* b2     = (const float*)d_in[10];
    const float* Wp     = (const float*)d_in[11];
    const float* bp     = (const float*)d_in[12];
    const float* ln_g   = (const float*)d_in[13];
    const float* ln_b   = (const float*)d_in[14];
    const float* Wc     = (const float*)d_in[15];
    const float* bc     = (const float*)d_in[16];
    const float* vc     = (const float*)d_in[17];
    const float* Wt     = (const float*)d_in[18];
    const float* btv    = (const float*)d_in[19];
    const float* vt     = (const float*)d_in[20];
    const float* Wih    = (const float*)d_in[21];
    const float* Whh    = (const float*)d_in[22];
    const float* bih    = (const float*)d_in[23];
    const float* bhh    = (const float*)d_in[24];
    const float* Wcls   = (const float*)d_in[25];
    const float* bcls   = (const float*)d_in[26];

    static int attr_done = 0;
    if (!attr_done) {
        cudaFuncSetAttribute(kAC, cudaFuncAttributeMaxDynamicSharedMemorySize,
                             2 * HALF * Gd * (int)sizeof(float));
        cudaFuncSetAttribute(kD, cudaFuncAttributeMaxDynamicSharedMemorySize,
                             SMAX * Gd * (int)sizeof(float));
        cudaFuncSetAttribute(k_lstm, cudaFuncAttributeMaxDynamicSharedMemorySize,
                             (64 * 512 + 8 * 512) * (int)sizeof(float));
        attr_done = 1;
    }

    k_setup<<<NCODE + 1 + BT, 128>>>(adj, code_x, prior, c_emb, W1);
    kAC<<<dim3(2, BT), 512, 2 * HALF * Gd * sizeof(float)>>>(
        prior, b1, W2, b2, Wp, bp, ln_g, ln_b, Wc, bc, vc);
    kD<<<BT, 256, SMAX * Gd * sizeof(float)>>>(Wih, bih, bhh);
    k_lstm<<<NB, 1024, (64 * 512 + 8 * 512) * sizeof(float)>>>(
        Whh, Wt, btv, vt, Wcls, bcls, (float*)d_out);
}

// round 3
// speedup vs baseline: 2.1333x; 1.3455x over previous
#include <cuda_runtime.h>
#include <math.h>

// Problem constants
#define NB 8
#define NT 8
#define BT 64
#define NCODE 1024
#define Gd 128
#define CSd 64
#define TAd 256
#define SMAX 96
#define CMAX 64
#define ROWS 32          // rows per kAC block
#define UTS 36           // padded transposed stride (floats, mult of 4)
#define LROWS 80         // Whh rows cached in k_lstm smem

// ---------------- device scratch ----------------
__device__ float d_EW1[NCODE * Gd];
__device__ float2 d_csr[NCODE * CMAX];
__device__ int    d_ccnt[NCODE];
__device__ int    d_act[BT * SMAX];
__device__ int    d_scnt[BT];
__device__ unsigned char d_rank[BT * NCODE];
__device__ float  d_psum;
__device__ float  d_logit[BT * SMAX];
__device__ float  d_co[BT * SMAX * Gd];
__device__ float  d_zx[BT * 512];

// =========================================================================
// K1: setup — EW1, adj CSR (2-pass MLP scan), active lists, prior sum
// grid 1089 x 128
// =========================================================================
__global__ void __launch_bounds__(128) k_setup(
    const float* __restrict__ adj, const float* __restrict__ code_x,
    const float* __restrict__ prior, const float* __restrict__ c_emb,
    const float* __restrict__ W1)
{
    int blk = blockIdx.x;
    int tid = threadIdx.x;
    int warp = tid >> 5, lane = tid & 31;

    if (blk < NCODE) {
        int n = blk;
        __shared__ float sc[CSd];
        __shared__ int wcnt[4];
        if (tid < CSd) sc[tid] = c_emb[n * CSd + tid];
        __syncthreads();
        float acc = 0.f;
        #pragma unroll 16
        for (int j = 0; j < CSd; ++j) acc += sc[j] * W1[j * Gd + tid];
        d_EW1[n * Gd + tid] = acc;

        // 2-pass CSR scan: 4 warps x 8 chunks, loads batched
        float vals[8];
        int myoff[8];
        int cnt = 0;
        #pragma unroll
        for (int it = 0; it < 8; ++it)
            vals[it] = adj[n * NCODE + warp * 256 + it * 32 + lane];
        #pragma unroll
        for (int it = 0; it < 8; ++it) {
            unsigned m = __ballot_sync(0xffffffffu, vals[it] != 0.f);
            myoff[it] = cnt + __popc(m & ((1u << lane) - 1u));
            cnt += __popc(m);
        }
        if (lane == 0) wcnt[warp] = cnt;
        __syncthreads();
        int base = 0;
        for (int w = 0; w < warp; ++w) base += wcnt[w];
        #pragma unroll
        for (int it = 0; it < 8; ++it) {
            if (vals[it] != 0.f) {
                int pos = base + myoff[it];
                if (pos < CMAX)
                    d_csr[n * CMAX + pos] =
                        make_float2(__int_as_float(warp * 256 + it * 32 + lane), vals[it]);
            }
        }
        if (tid == 0) d_ccnt[n] = min(wcnt[0] + wcnt[1] + wcnt[2] + wcnt[3], CMAX);
    } else if (blk == NCODE) {
        __shared__ float sr[128];
        float s = 0.f;
        for (int i = tid; i < NCODE; i += 128) s += prior[i];
        sr[tid] = s; __syncthreads();
        for (int o = 64; o > 0; o >>= 1) {
            if (tid < o) sr[tid] += sr[tid + o];
            __syncthreads();
        }
        if (tid == 0) d_psum = sr[0];
    } else {
        int bt = blk - (NCODE + 1);
        __shared__ int wcnt2[4];
        for (int i = tid; i < NCODE; i += 128) d_rank[bt * NCODE + i] = 0xFF;
        __syncthreads();
        float vals[8];
        int myoff[8];
        int cnt = 0;
        #pragma unroll
        for (int it = 0; it < 8; ++it)
            vals[it] = code_x[bt * NCODE + warp * 256 + it * 32 + lane];
        #pragma unroll
        for (int it = 0; it < 8; ++it) {
            unsigned m = __ballot_sync(0xffffffffu, vals[it] != 0.f);
            myoff[it] = cnt + __popc(m & ((1u << lane) - 1u));
            cnt += __popc(m);
        }
        if (lane == 0) wcnt2[warp] = cnt;
        __syncthreads();
        int base = 0;
        for (int w = 0; w < warp; ++w) base += wcnt2[w];
        #pragma unroll
        for (int it = 0; it < 8; ++it) {
            if (vals[it] != 0.f) {
                int pos = base + myoff[it];
                int idx = warp * 256 + it * 32 + lane;
                if (pos < SMAX) {
                    d_act[bt * SMAX + pos] = idx;
                    d_rank[bt * NCODE + idx] = (unsigned char)pos;
                }
            }
        }
        if (tid == 0)
            d_scnt[bt] = min(wcnt2[0] + wcnt2[1] + wcnt2[2] + wcnt2[3], SMAX);
    }
}

// =========================================================================
// K2: kAC — sparse GCN rows + co GEMM + LN residual + logits.
// grid (3, 64) x 512, dyn smem: sUT[128][UTS] + sCo[32][128] + sCoT[128][UTS]
// =========================================================================
__global__ void __launch_bounds__(512) kAC(
    const float* __restrict__ prior, const float* __restrict__ b1,
    const float* __restrict__ W2,  const float* __restrict__ b2,
    const float* __restrict__ Wp,  const float* __restrict__ bp,
    const float* __restrict__ lng, const float* __restrict__ lnb,
    const float* __restrict__ Wc,  const float* __restrict__ bc,
    const float* __restrict__ vc)
{
    extern __shared__ float dyn[];
    float* sUT  = dyn;                       // [128][UTS]
    float* sCo  = dyn + 128 * UTS;           // [32][128]
    float* sCoT = sCo + ROWS * Gd;           // [128][UTS]
    __shared__ unsigned char sRank[NCODE];
    __shared__ float sPr[ROWS];
    __shared__ float sRedC[4][4][8];

    int bt = blockIdx.y;
    int base = blockIdx.x * ROWS;
    int tid = threadIdx.x;
    int warp = tid >> 5, lane = tid & 31;
    int s = tid >> 7, g = tid & 127;         // slot 0..3, feature dim
    int wis = warp & 3;
    int S = d_scnt[bt];
    int rows = min(S - base, ROWS);
    if (rows <= 0) return;

    for (int i = tid; i < NCODE; i += 512) sRank[i] = d_rank[bt * NCODE + i];
    if (tid < ROWS)
        sPr[tid] = (tid < rows) ? prior[d_act[bt * SMAX + base + tid]] / d_psum : 0.f;
    __syncthreads();

    // ---- Phase A: u rows -> transposed smem ----
    {
        float bb[4];
        #pragma unroll
        for (int q = 0; q < 4; ++q) bb[q] = b1[lane + 32 * q];
        for (int mi = warp; mi < ROWS; mi += 16) {
            if (mi < rows) {
                int am = d_act[bt * SMAX + base + mi];
                float acc[4] = {0.f, 0.f, 0.f, 0.f};
                int cm = d_ccnt[am];
                const float2* rowm = d_csr + am * CMAX;
                for (int e = 0; e < cm; ++e) {
                    float2 cv = rowm[e];
                    int n = __float_as_int(cv.x);
                    float v = cv.y;
                    float hv[4];
                    #pragma unroll
                    for (int q = 0; q < 4; ++q) hv[q] = bb[q];
                    int cn = d_ccnt[n];
                    const float2* rown = d_csr + n * CMAX;
                    int e2 = 0;
                    for (; e2 + 4 <= cn; e2 += 4) {
                        float2 c0 = rown[e2], c1 = rown[e2 + 1],
                               c2 = rown[e2 + 2], c3 = rown[e2 + 3];
                        int k0 = __float_as_int(c0.x), k1 = __float_as_int(c1.x);
                        int k2 = __float_as_int(c2.x), k3 = __float_as_int(c3.x);
                        unsigned char r0 = sRank[k0], r1 = sRank[k1];
                        unsigned char r2 = sRank[k2], r3 = sRank[k3];
                        if (r0 != 0xFF) {
                            const float* ew = d_EW1 + k0 * Gd;
                            #pragma unroll
                            for (int q = 0; q < 4; ++q) hv[q] += c0.y * ew[lane + 32 * q];
                        }
                        if (r1 != 0xFF) {
                            const float* ew = d_EW1 + k1 * Gd;
                            #pragma unroll
                            for (int q = 0; q < 4; ++q) hv[q] += c1.y * ew[lane + 32 * q];
                        }
                        if (r2 != 0xFF) {
                            const float* ew = d_EW1 + k2 * Gd;
                            #pragma unroll
                            for (int q = 0; q < 4; ++q) hv[q] += c2.y * ew[lane + 32 * q];
                        }
                        if (r3 != 0xFF) {
                            const float* ew = d_EW1 + k3 * Gd;
                            #pragma unroll
                            for (int q = 0; q < 4; ++q) hv[q] += c3.y * ew[lane + 32 * q];
                        }
                    }
                    for (; e2 < cn; ++e2) {
                        float2 c0 = rown[e2];
                        int k0 = __float_as_int(c0.x);
                        if (sRank[k0] != 0xFF) {
                            const float* ew = d_EW1 + k0 * Gd;
                            #pragma unroll
                            for (int q = 0; q < 4; ++q) hv[q] += c0.y * ew[lane + 32 * q];
                        }
                    }
                    #pragma unroll
                    for (int q = 0; q < 4; ++q) acc[q] += v * fmaxf(hv[q], 0.f);
                }
                #pragma unroll
                for (int q = 0; q < 4; ++q)
                    sUT[(lane + 32 * q) * UTS + mi] = acc[q];
            } else {
                #pragma unroll
                for (int q = 0; q < 4; ++q) {
                    sUT[(lane + 32 * q) * UTS + mi] = 0.f;
                    sCoT[(lane + 32 * q) * UTS + mi] = 0.f;
                }
            }
        }
    }
    __syncthreads();

    // ---- Phase B: co = u @ W2 + b2 (vectorized transposed reads) ----
    {
        float acc[8];
        #pragma unroll
        for (int i = 0; i < 8; ++i) acc[i] = 0.f;
        #pragma unroll 4
        for (int j = 0; j < Gd; ++j) {
            float w = W2[j * Gd + g];
            float4 u0 = *reinterpret_cast<const float4*>(&sUT[j * UTS + s * 8]);
            float4 u1 = *reinterpret_cast<const float4*>(&sUT[j * UTS + s * 8 + 4]);
            acc[0] += u0.x * w; acc[1] += u0.y * w; acc[2] += u0.z * w; acc[3] += u0.w * w;
            acc[4] += u1.x * w; acc[5] += u1.y * w; acc[6] += u1.z * w; acc[7] += u1.w * w;
        }
        float b2g = b2[g];
        #pragma unroll
        for (int i = 0; i < 8; ++i)
            sCo[(s * 8 + i) * Gd + g] = acc[i] + b2g;
    }
    __syncthreads();

    // ---- Phase C: prior modulation + LN + leaky relu residual ----
    {
        float wpv[4], bpv[4], lg[4], lb[4];
        #pragma unroll
        for (int q = 0; q < 4; ++q) {
            int gg = lane + 32 * q;
            wpv[q] = Wp[gg]; bpv[q] = bp[gg]; lg[q] = lng[gg]; lb[q] = lnb[gg];
        }
        for (int mi = warp; mi < rows; mi += 16) {
            float p = sPr[mi];
            float co[4], cw[4];
            float sum = 0.f;
            #pragma unroll
            for (int q = 0; q < 4; ++q) {
                co[q] = sCo[mi * Gd + lane + 32 * q];
                cw[q] = co[q] * (p * wpv[q] + bpv[q]);
                sum += cw[q];
            }
            #pragma unroll
            for (int o = 16; o > 0; o >>= 1) sum += __shfl_xor_sync(0xffffffffu, sum, o);
            float mu = sum * (1.f / 128.f);
            float vs = 0.f;
            #pragma unroll
            for (int q = 0; q < 4; ++q) { float d = cw[q] - mu; vs += d * d; }
            #pragma unroll
            for (int o = 16; o > 0; o >>= 1) vs += __shfl_xor_sync(0xffffffffu, vs, o);
            float inv = rsqrtf(vs * (1.f / 128.f) + 1e-5f);
            #pragma unroll
            for (int q = 0; q < 4; ++q) {
                float nv = (cw[q] - mu) * inv * lg[q] + lb[q];
                nv = (nv >= 0.f) ? nv : 0.01f * nv;
                float r = co[q] + nv;
                sCo[mi * Gd + lane + 32 * q] = r;
                sCoT[(lane + 32 * q) * UTS + mi] = r;
            }
        }
    }
    __syncthreads();

    // ---- Phase C2: logits = tanh(co@Wc + bc) @ vc ----
    {
        float acc[8];
        #pragma unroll
        for (int i = 0; i < 8; ++i) acc[i] = 0.f;
        #pragma unroll 4
        for (int j = 0; j < Gd; ++j) {
            float w = Wc[j * Gd + g];
            float4 u0 = *reinterpret_cast<const float4*>(&sCoT[j * UTS + s * 8]);
            float4 u1 = *reinterpret_cast<const float4*>(&sCoT[j * UTS + s * 8 + 4]);
            acc[0] += u0.x * w; acc[1] += u0.y * w; acc[2] += u0.z * w; acc[3] += u0.w * w;
            acc[4] += u1.x * w; acc[5] += u1.y * w; acc[6] += u1.z * w; acc[7] += u1.w * w;
        }
        float bcg = bc[g], vcg = vc[g];
        #pragma unroll
        for (int i = 0; i < 8; ++i) {
            float tv = tanhf(acc[i] + bcg) * vcg;
            #pragma unroll
            for (int o = 16; o > 0; o >>= 1)
                tv += __shfl_xor_sync(0xffffffffu, tv, o);
            if (lane == 0) sRedC[s][wis][i] = tv;
        }
        __syncthreads();
        if (tid < 32) {
            int s2 = tid >> 3, i2 = tid & 7;
            int row = s2 * 8 + i2;
            if (row < rows)
                d_logit[bt * SMAX + base + row] =
                    sRedC[s2][0][i2] + sRedC[s2][1][i2] +
                    sRedC[s2][2][i2] + sRedC[s2][3][i2];
        }
    }

    // ---- write co rows ----
    for (int idx = tid; idx < rows * Gd; idx += 512)
        d_co[(bt * SMAX + base) * Gd + idx] = sCo[idx];
}

// =========================================================================
// K3: kD — softmax, visit, zx = visit@Wih+bih+bhh. grid 64 x 512
// =========================================================================
__global__ void __launch_bounds__(512) kD(
    const float* __restrict__ Wih, const float* __restrict__ bih,
    const float* __restrict__ bhh)
{
    extern __shared__ float sCoD[];
    __shared__ float sAttn[SMAX];
    __shared__ float sVis[Gd];

    int bt = blockIdx.x, tid = threadIdx.x;
    int S = d_scnt[bt];

    for (int idx = tid; idx < S * Gd; idx += 512)
        sCoD[idx] = d_co[bt * SMAX * Gd + idx];

    if (tid < 32) {
        float mx = -3.0e38f;
        for (int m = tid; m < S; m += 32) {
            float l = d_logit[bt * SMAX + m];
            sAttn[m] = l;
            mx = fmaxf(mx, l);
        }
        #pragma unroll
        for (int o = 16; o > 0; o >>= 1)
            mx = fmaxf(mx, __shfl_xor_sync(0xffffffffu, mx, o));
        float se = 0.f;
        for (int m = tid; m < S; m += 32) {
            float e = expf(sAttn[m] - mx);
            sAttn[m] = e; se += e;
        }
        #pragma unroll
        for (int o = 16; o > 0; o >>= 1) se += __shfl_xor_sync(0xffffffffu, se, o);
        float inv = 1.f / se;
        for (int m = tid; m < S; m += 32) sAttn[m] *= inv;
    }
    __syncthreads();

    if (tid < Gd) {
        float v = 0.f;
        for (int m = 0; m < S; ++m) v += sAttn[m] * sCoD[m * Gd + tid];
        sVis[tid] = v;
    }
    __syncthreads();

    {
        int j = tid;
        float z = bih[j] + bhh[j];
        #pragma unroll 4
        for (int k = 0; k < Gd; ++k) z += sVis[k] * Wih[k * 512 + j];
        d_zx[bt * 512 + j] = z;
    }
}

// =========================================================================
// K4: LSTM + temporal attention + classifier. grid 8 x 1024
// dyn smem: Whh[80][512] (reused for Wt[128][256]) + zx[8][512] + zp[8][512]
// =========================================================================
__global__ void __launch_bounds__(1024) k_lstm(
    const float* __restrict__ Whh, const float* __restrict__ Wt,
    const float* __restrict__ btv, const float* __restrict__ vt,
    const float* __restrict__ Wcls, const float* __restrict__ bcls,
    float* __restrict__ out)
{
    extern __shared__ float dynl[];
    float* sW  = dynl;                    // LROWS*512 floats (later Wt)
    float* szx = dynl + LROWS * 512;      // [8][512]
    float* szp = szx + 8 * 512;           // [8][512]
    __shared__ float sh[128], scst[128], shs[8 * 128], sz[512];
    __shared__ float sU8[8], sRedT[8][8], sRedF[4];

    int b = blockIdx.x, tid = threadIdx.x;
    int jq = tid & 127, kh = tid >> 7;
    int warp = tid >> 5, lane = tid & 31;
    const float4* W4 = reinterpret_cast<const float4*>(Whh);

    #pragma unroll
    for (int i = 0; i < LROWS / 8; ++i)
        reinterpret_cast<float4*>(sW)[tid + 1024 * i] = W4[tid + 1024 * i];
    reinterpret_cast<float4*>(szx)[tid] =
        reinterpret_cast<const float4*>(d_zx + b * 4096)[tid];
    if (tid < 128) { sh[tid] = 0.f; scst[tid] = 0.f; }
    __syncthreads();

    for (int t = 0; t < 8; ++t) {
        if (t > 0) {
            int k0 = kh * 16;
            float4 z4 = make_float4(0.f, 0.f, 0.f, 0.f);
            if (kh < LROWS / 16) {
                #pragma unroll
                for (int kk = 0; kk < 16; ++kk) {
                    float hv = sh[k0 + kk];
                    float4 w = reinterpret_cast<const float4*>(sW)[(k0 + kk) * 128 + jq];
                    z4.x += hv * w.x; z4.y += hv * w.y;
                    z4.z += hv * w.z; z4.w += hv * w.w;
                }
            } else {
                float4 wr[8];
                #pragma unroll
                for (int kk = 0; kk < 8; ++kk) wr[kk] = W4[(k0 + kk) * 128 + jq];
                #pragma unroll
                for (int kk = 0; kk < 8; ++kk) {
                    float hv = sh[k0 + kk];
                    z4.x += hv * wr[kk].x; z4.y += hv * wr[kk].y;
                    z4.z += hv * wr[kk].z; z4.w += hv * wr[kk].w;
                }
                #pragma unroll
                for (int kk = 0; kk < 8; ++kk) wr[kk] = W4[(k0 + 8 + kk) * 128 + jq];
                #pragma unroll
                for (int kk = 0; kk < 8; ++kk) {
                    float hv = sh[k0 + 8 + kk];
                    z4.x += hv * wr[kk].x; z4.y += hv * wr[kk].y;
                    z4.z += hv * wr[kk].z; z4.w += hv * wr[kk].w;
                }
            }
            reinterpret_cast<float4*>(szp + kh * 512)[jq] = z4;
        }
        __syncthreads();
        if (tid < 512) {
            float z = szx[t * 512 + tid];
            if (t > 0) {
                #pragma unroll
                for (int q = 0; q < 8; ++q) z += szp[q * 512 + tid];
            }
            float a;
            if (tid < 256)      a = 1.f / (1.f + expf(-z));
            else if (tid < 384) a = tanhf(z);
            else                a = 1.f / (1.f + expf(-z));
            sz[tid] = a;
        }
        __syncthreads();
        if (tid < 128) {
            float c = sz[tid + 128] * scst[tid] + sz[tid] * sz[tid + 256];
            scst[tid] = c;
            float h = sz[tid + 384] * tanhf(c);
            sh[tid] = h;
            shs[t * 128 + tid] = h;
        }
        __syncthreads();
    }

    // ---- load Wt into sW, attention ----
    #pragma unroll
    for (int i = 0; i < 8; ++i)
        reinterpret_cast<float4*>(sW)[tid + 1024 * i] =
            reinterpret_cast<const float4*>(Wt)[tid + 1024 * i];
    __syncthreads();

    #pragma unroll
    for (int rep = 0; rep < 2; ++rep) {
        int t = (tid >> 8) + rep * 4;
        int ta = tid & 255;
        float a = btv[ta];
        #pragma unroll 8
        for (int h = 0; h < 128; ++h) a += shs[t * 128 + h] * sW[h * TAd + ta];
        a = tanhf(a) * vt[ta];
        #pragma unroll
        for (int o = 16; o > 0; o >>= 1) a += __shfl_xor_sync(0xffffffffu, a, o);
        if (lane == 0) sRedT[t][warp & 7] = a;
    }
    __syncthreads();
    if (tid < 8) {
        float sum = 0.f;
        #pragma unroll
        for (int w = 0; w < 8; ++w) sum += sRedT[tid][w];
        sU8[tid] = sum;
    }
    __syncthreads();
    if (tid == 0) {
        float mx = -3.0e38f;
        #pragma unroll
        for (int t = 0; t < 8; ++t) mx = fmaxf(mx, sU8[t]);
        float se = 0.f;
        #pragma unroll
        for (int t = 0; t < 8; ++t) { float e = expf(sU8[t] - mx); sU8[t] = e; se += e; }
        float inv = 1.f / se;
        #pragma unroll
        for (int t = 0; t < 8; ++t) sU8[t] *= inv;
    }
    __syncthreads();

    float partial = 0.f;
    if (tid < 128) {
        float p = 0.f;
        #pragma unroll
        for (int t = 0; t < 8; ++t) p += sU8[t] * shs[t * 128 + tid];
        partial = p * Wcls[tid];
    }
    #pragma unroll
    for (int o = 16; o > 0; o >>= 1) partial += __shfl_xor_sync(0xffffffffu, partial, o);
    if (lane == 0 && warp < 4) sRedF[warp] = partial;
    __syncthreads();
    if (tid == 0) out[b] = sRedF[0] + sRedF[1] + sRedF[2] + sRedF[3] + bcls[0];
}

// =========================================================================
extern "C" void kernel_launch(void* const* d_in, const int* in_sizes, int n_in,
                              void* d_out, int out_size)
{
    const float* code_x = (const float*)d_in[0];
    const float* prior  = (const float*)d_in[4];
    const float* adj    = (const float*)d_in[5];
    const float* c_emb  = (const float*)d_in[6];
    const float* W1     = (const float*)d_in[7];
    const float* b1     = (const float*)d_in[8];
    const float* W2     = (const float*)d_in[9];
    const float* b2     = (const float*)d_in[10];
    const float* Wp     = (const float*)d_in[11];
    const float* bp     = (const float*)d_in[12];
    const float* ln_g   = (const float*)d_in[13];
    const float* ln_b   = (const float*)d_in[14];
    const float* Wc     = (const float*)d_in[15];
    const float* bc     = (const float*)d_in[16];
    const float* vc     = (const float*)d_in[17];
    const float* Wt     = (const float*)d_in[18];
    const float* btv    = (const float*)d_in[19];
    const float* vt     = (const float*)d_in[20];
    const float* Wih    = (const float*)d_in[21];
    const float* Whh    = (const float*)d_in[22];
    const float* bih    = (const float*)d_in[23];
    const float* bhh    = (const float*)d_in[24];
    const float* Wcls   = (const float*)d_in[25];
    const float* bcls   = (const float*)d_in[26];

    const int AC_SMEM = (128 * UTS + ROWS * Gd + 128 * UTS) * (int)sizeof(float);
    const int D_SMEM  = SMAX * Gd * (int)sizeof(float);
    const int L_SMEM  = (LROWS * 512 + 2 * 8 * 512) * (int)sizeof(float);

    cudaFuncSetAttribute(kAC, cudaFuncAttributeMaxDynamicSharedMemorySize, AC_SMEM);
    cudaFuncSetAttribute(kD, cudaFuncAttributeMaxDynamicSharedMemorySize, D_SMEM);
    cudaFuncSetAttribute(k_lstm, cudaFuncAttributeMaxDynamicSharedMemorySize, L_SMEM);

    k_setup<<<NCODE + 1 + BT, 128>>>(adj, code_x, prior, c_emb, W1);
    kAC<<<dim3(3, BT), 512, AC_SMEM>>>(
        prior, b1, W2, b2, Wp, bp, ln_g, ln_b, Wc, bc, vc);
    kD<<<BT, 512, D_SMEM>>>(Wih, bih, bhh);
    k_lstm<<<NB, 1024, L_SMEM>>>(Whh, Wt, btv, vt, Wcls, bcls, (float*)d_out);
}

// round 4
// speedup vs baseline: 2.3049x; 1.0804x over previous
#include <cuda_runtime.h>
#include <math.h>

// Problem constants
#define NB 8
#define NT 8
#define BT 64
#define NCODE 1024
#define Gd 128
#define CSd 64
#define TAd 256
#define SMAX 96
#define CMAX 64
#define ROWS 32          // rows per kAC block
#define UTS 36           // padded transposed stride (floats, mult of 4)
#define KREG 80          // Whh rows held in registers in k_lstm
#define KTAIL 48         // Whh rows held in smem in k_lstm

// ---------------- device scratch ----------------
__device__ float d_EW1[NCODE * Gd];
__device__ float2 d_csr[NCODE * CMAX];
__device__ int    d_ccnt[NCODE];
__device__ int    d_act[BT * SMAX];
__device__ int    d_scnt[BT];
__device__ unsigned char d_rank[BT * NCODE];
__device__ float  d_psum;
__device__ float  d_logit[BT * SMAX];
__device__ float  d_co[BT * SMAX * Gd];
__device__ float  d_zx[BT * 512];

// =========================================================================
// K1: setup — EW1, adj CSR (2-pass MLP scan), active lists, prior sum
// =========================================================================
__global__ void __launch_bounds__(128) k_setup(
    const float* __restrict__ adj, const float* __restrict__ code_x,
    const float* __restrict__ prior, const float* __restrict__ c_emb,
    const float* __restrict__ W1)
{
    int blk = blockIdx.x;
    int tid = threadIdx.x;
    int warp = tid >> 5, lane = tid & 31;

    if (blk < NCODE) {
        int n = blk;
        __shared__ float sc[CSd];
        __shared__ int wcnt[4];
        if (tid < CSd) sc[tid] = c_emb[n * CSd + tid];
        __syncthreads();
        float acc = 0.f;
        #pragma unroll 16
        for (int j = 0; j < CSd; ++j) acc += sc[j] * W1[j * Gd + tid];
        d_EW1[n * Gd + tid] = acc;

        float vals[8];
        int myoff[8];
        int cnt = 0;
        #pragma unroll
        for (int it = 0; it < 8; ++it)
            vals[it] = adj[n * NCODE + warp * 256 + it * 32 + lane];
        #pragma unroll
        for (int it = 0; it < 8; ++it) {
            unsigned m = __ballot_sync(0xffffffffu, vals[it] != 0.f);
            myoff[it] = cnt + __popc(m & ((1u << lane) - 1u));
            cnt += __popc(m);
        }
        if (lane == 0) wcnt[warp] = cnt;
        __syncthreads();
        int base = 0;
        for (int w = 0; w < warp; ++w) base += wcnt[w];
        #pragma unroll
        for (int it = 0; it < 8; ++it) {
            if (vals[it] != 0.f) {
                int pos = base + myoff[it];
                if (pos < CMAX)
                    d_csr[n * CMAX + pos] =
                        make_float2(__int_as_float(warp * 256 + it * 32 + lane), vals[it]);
            }
        }
        if (tid == 0) d_ccnt[n] = min(wcnt[0] + wcnt[1] + wcnt[2] + wcnt[3], CMAX);
    } else if (blk == NCODE) {
        __shared__ float sr[128];
        float s = 0.f;
        for (int i = tid; i < NCODE; i += 128) s += prior[i];
        sr[tid] = s; __syncthreads();
        for (int o = 64; o > 0; o >>= 1) {
            if (tid < o) sr[tid] += sr[tid + o];
            __syncthreads();
        }
        if (tid == 0) d_psum = sr[0];
    } else {
        int bt = blk - (NCODE + 1);
        __shared__ int wcnt2[4];
        for (int i = tid; i < NCODE; i += 128) d_rank[bt * NCODE + i] = 0xFF;
        __syncthreads();
        float vals[8];
        int myoff[8];
        int cnt = 0;
        #pragma unroll
        for (int it = 0; it < 8; ++it)
            vals[it] = code_x[bt * NCODE + warp * 256 + it * 32 + lane];
        #pragma unroll
        for (int it = 0; it < 8; ++it) {
            unsigned m = __ballot_sync(0xffffffffu, vals[it] != 0.f);
            myoff[it] = cnt + __popc(m & ((1u << lane) - 1u));
            cnt += __popc(m);
        }
        if (lane == 0) wcnt2[warp] = cnt;
        __syncthreads();
        int base = 0;
        for (int w = 0; w < warp; ++w) base += wcnt2[w];
        #pragma unroll
        for (int it = 0; it < 8; ++it) {
            if (vals[it] != 0.f) {
                int pos = base + myoff[it];
                int idx = warp * 256 + it * 32 + lane;
                if (pos < SMAX) {
                    d_act[bt * SMAX + pos] = idx;
                    d_rank[bt * NCODE + idx] = (unsigned char)pos;
                }
            }
        }
        if (tid == 0)
            d_scnt[bt] = min(wcnt2[0] + wcnt2[1] + wcnt2[2] + wcnt2[3], SMAX);
    }
}

// =========================================================================
// K2: kAC — sparse GCN rows + co GEMM + LN residual + logits. grid (3,64)x512
// =========================================================================
__global__ void __launch_bounds__(512) kAC(
    const float* __restrict__ prior, const float* __restrict__ b1,
    const float* __restrict__ W2,  const float* __restrict__ b2,
    const float* __restrict__ Wp,  const float* __restrict__ bp,
    const float* __restrict__ lng, const float* __restrict__ lnb,
    const float* __restrict__ Wc,  const float* __restrict__ bc,
    const float* __restrict__ vc)
{
    extern __shared__ float dyn[];
    float* sUT  = dyn;                       // [128][UTS]
    float* sCo  = dyn + 128 * UTS;           // [32][128]
    float* sCoT = sCo + ROWS * Gd;           // [128][UTS]
    __shared__ unsigned char sRank[NCODE];
    __shared__ float sPr[ROWS];
    __shared__ float sRedC[4][4][8];

    int bt = blockIdx.y;
    int base = blockIdx.x * ROWS;
    int tid = threadIdx.x;
    int warp = tid >> 5, lane = tid & 31;
    int s = tid >> 7, g = tid & 127;
    int wis = warp & 3;
    int S = d_scnt[bt];
    int rows = min(S - base, ROWS);
    if (rows <= 0) return;

    for (int i = tid; i < NCODE; i += 512) sRank[i] = d_rank[bt * NCODE + i];
    if (tid < ROWS)
        sPr[tid] = (tid < rows) ? prior[d_act[bt * SMAX + base + tid]] / d_psum : 0.f;
    __syncthreads();

    // ---- Phase A: u rows -> transposed smem ----
    {
        float bb[4];
        #pragma unroll
        for (int q = 0; q < 4; ++q) bb[q] = b1[lane + 32 * q];
        for (int mi = warp; mi < ROWS; mi += 16) {
            if (mi < rows) {
                int am = d_act[bt * SMAX + base + mi];
                float acc[4] = {0.f, 0.f, 0.f, 0.f};
                int cm = d_ccnt[am];
                const float2* rowm = d_csr + am * CMAX;
                for (int e = 0; e < cm; ++e) {
                    float2 cv = rowm[e];
                    int n = __float_as_int(cv.x);
                    float v = cv.y;
                    float hv[4];
                    #pragma unroll
                    for (int q = 0; q < 4; ++q) hv[q] = bb[q];
                    int cn = d_ccnt[n];
                    const float2* rown = d_csr + n * CMAX;
                    int e2 = 0;
                    for (; e2 + 4 <= cn; e2 += 4) {
                        float2 c0 = rown[e2], c1 = rown[e2 + 1],
                               c2 = rown[e2 + 2], c3 = rown[e2 + 3];
                        int k0 = __float_as_int(c0.x), k1 = __float_as_int(c1.x);
                        int k2 = __float_as_int(c2.x), k3 = __float_as_int(c3.x);
                        unsigned char r0 = sRank[k0], r1 = sRank[k1];
                        unsigned char r2 = sRank[k2], r3 = sRank[k3];
                        if (r0 != 0xFF) {
                            const float* ew = d_EW1 + k0 * Gd;
                            #pragma unroll
                            for (int q = 0; q < 4; ++q) hv[q] += c0.y * ew[lane + 32 * q];
                        }
                        if (r1 != 0xFF) {
                            const float* ew = d_EW1 + k1 * Gd;
                            #pragma unroll
                            for (int q = 0; q < 4; ++q) hv[q] += c1.y * ew[lane + 32 * q];
                        }
                        if (r2 != 0xFF) {
                            const float* ew = d_EW1 + k2 * Gd;
                            #pragma unroll
                            for (int q = 0; q < 4; ++q) hv[q] += c2.y * ew[lane + 32 * q];
                        }
                        if (r3 != 0xFF) {
                            const float* ew = d_EW1 + k3 * Gd;
                            #pragma unroll
                            for (int q = 0; q < 4; ++q) hv[q] += c3.y * ew[lane + 32 * q];
                        }
                    }
                    for (; e2 < cn; ++e2) {
                        float2 c0 = rown[e2];
                        int k0 = __float_as_int(c0.x);
                        if (sRank[k0] != 0xFF) {
                            const float* ew = d_EW1 + k0 * Gd;
                            #pragma unroll
                            for (int q = 0; q < 4; ++q) hv[q] += c0.y * ew[lane + 32 * q];
                        }
                    }
                    #pragma unroll
                    for (int q = 0; q < 4; ++q) acc[q] += v * fmaxf(hv[q], 0.f);
                }
                #pragma unroll
                for (int q = 0; q < 4; ++q)
                    sUT[(lane + 32 * q) * UTS + mi] = acc[q];
            } else {
                #pragma unroll
                for (int q = 0; q < 4; ++q) {
                    sUT[(lane + 32 * q) * UTS + mi] = 0.f;
                    sCoT[(lane + 32 * q) * UTS + mi] = 0.f;
                }
            }
        }
    }
    __syncthreads();

    // ---- Phase B: co = u @ W2 + b2 ----
    {
        float acc[8];
        #pragma unroll
        for (int i = 0; i < 8; ++i) acc[i] = 0.f;
        #pragma unroll 4
        for (int j = 0; j < Gd; ++j) {
            float w = W2[j * Gd + g];
            float4 u0 = *reinterpret_cast<const float4*>(&sUT[j * UTS + s * 8]);
            float4 u1 = *reinterpret_cast<const float4*>(&sUT[j * UTS + s * 8 + 4]);
            acc[0] += u0.x * w; acc[1] += u0.y * w; acc[2] += u0.z * w; acc[3] += u0.w * w;
            acc[4] += u1.x * w; acc[5] += u1.y * w; acc[6] += u1.z * w; acc[7] += u1.w * w;
        }
        float b2g = b2[g];
        #pragma unroll
        for (int i = 0; i < 8; ++i)
            sCo[(s * 8 + i) * Gd + g] = acc[i] + b2g;
    }
    __syncthreads();

    // ---- Phase C: prior modulation + LN + leaky relu residual ----
    {
        float wpv[4], bpv[4], lg[4], lb[4];
        #pragma unroll
        for (int q = 0; q < 4; ++q) {
            int gg = lane + 32 * q;
            wpv[q] = Wp[gg]; bpv[q] = bp[gg]; lg[q] = lng[gg]; lb[q] = lnb[gg];
        }
        for (int mi = warp; mi < rows; mi += 16) {
            float p = sPr[mi];
            float co[4], cw[4];
            float sum = 0.f;
            #pragma unroll
            for (int q = 0; q < 4; ++q) {
                co[q] = sCo[mi * Gd + lane + 32 * q];
                cw[q] = co[q] * (p * wpv[q] + bpv[q]);
                sum += cw[q];
            }
            #pragma unroll
            for (int o = 16; o > 0; o >>= 1) sum += __shfl_xor_sync(0xffffffffu, sum, o);
            float mu = sum * (1.f / 128.f);
            float vs = 0.f;
            #pragma unroll
            for (int q = 0; q < 4; ++q) { float d = cw[q] - mu; vs += d * d; }
            #pragma unroll
            for (int o = 16; o > 0; o >>= 1) vs += __shfl_xor_sync(0xffffffffu, vs, o);
            float inv = rsqrtf(vs * (1.f / 128.f) + 1e-5f);
            #pragma unroll
            for (int q = 0; q < 4; ++q) {
                float nv = (cw[q] - mu) * inv * lg[q] + lb[q];
                nv = (nv >= 0.f) ? nv : 0.01f * nv;
                float r = co[q] + nv;
                sCo[mi * Gd + lane + 32 * q] = r;
                sCoT[(lane + 32 * q) * UTS + mi] = r;
            }
        }
    }
    __syncthreads();

    // ---- Phase C2: logits = tanh(co@Wc + bc) @ vc ----
    {
        float acc[8];
        #pragma unroll
        for (int i = 0; i < 8; ++i) acc[i] = 0.f;
        #pragma unroll 4
        for (int j = 0; j < Gd; ++j) {
            float w = Wc[j * Gd + g];
            float4 u0 = *reinterpret_cast<const float4*>(&sCoT[j * UTS + s * 8]);
            float4 u1 = *reinterpret_cast<const float4*>(&sCoT[j * UTS + s * 8 + 4]);
            acc[0] += u0.x * w; acc[1] += u0.y * w; acc[2] += u0.z * w; acc[3] += u0.w * w;
            acc[4] += u1.x * w; acc[5] += u1.y * w; acc[6] += u1.z * w; acc[7] += u1.w * w;
        }
        float bcg = bc[g], vcg = vc[g];
        #pragma unroll
        for (int i = 0; i < 8; ++i) {
            float tv = tanhf(acc[i] + bcg) * vcg;
            #pragma unroll
            for (int o = 16; o > 0; o >>= 1)
                tv += __shfl_xor_sync(0xffffffffu, tv, o);
            if (lane == 0) sRedC[s][wis][i] = tv;
        }
        __syncthreads();
        if (tid < 32) {
            int s2 = tid >> 3, i2 = tid & 7;
            int row = s2 * 8 + i2;
            if (row < rows)
                d_logit[bt * SMAX + base + row] =
                    sRedC[s2][0][i2] + sRedC[s2][1][i2] +
                    sRedC[s2][2][i2] + sRedC[s2][3][i2];
        }
    }

    for (int idx = tid; idx < rows * Gd; idx += 512)
        d_co[(bt * SMAX + base) * Gd + idx] = sCo[idx];
}

// =========================================================================
// K3: kD — softmax, visit, zx. grid 64 x 512
// =========================================================================
__global__ void __launch_bounds__(512) kD(
    const float* __restrict__ Wih, const float* __restrict__ bih,
    const float* __restrict__ bhh)
{
    extern __shared__ float sCoD[];
    __shared__ float sAttn[SMAX];
    __shared__ float sVis[Gd];

    int bt = blockIdx.x, tid = threadIdx.x;
    int S = d_scnt[bt];

    for (int idx = tid; idx < S * Gd; idx += 512)
        sCoD[idx] = d_co[bt * SMAX * Gd + idx];

    if (tid < 32) {
        float mx = -3.0e38f;
        for (int m = tid; m < S; m += 32) {
            float l = d_logit[bt * SMAX + m];
            sAttn[m] = l;
            mx = fmaxf(mx, l);
        }
        #pragma unroll
        for (int o = 16; o > 0; o >>= 1)
            mx = fmaxf(mx, __shfl_xor_sync(0xffffffffu, mx, o));
        float se = 0.f;
        for (int m = tid; m < S; m += 32) {
            float e = expf(sAttn[m] - mx);
            sAttn[m] = e; se += e;
        }
        #pragma unroll
        for (int o = 16; o > 0; o >>= 1) se += __shfl_xor_sync(0xffffffffu, se, o);
        float inv = 1.f / se;
        for (int m = tid; m < S; m += 32) sAttn[m] *= inv;
    }
    __syncthreads();

    if (tid < Gd) {
        float v = 0.f;
        for (int m = 0; m < S; ++m) v += sAttn[m] * sCoD[m * Gd + tid];
        sVis[tid] = v;
    }
    __syncthreads();

    {
        int j = tid;
        float z = bih[j] + bhh[j];
        #pragma unroll 4
        for (int k = 0; k < Gd; ++k) z += sVis[k] * Wih[k * 512 + j];
        d_zx[bt * 512 + j] = z;
    }
}

// =========================================================================
// K4: LSTM + temporal attention + classifier. grid 8 x 512.
// Whh columns: 80 rows in registers per thread, 48 rows in smem.
// dyn smem: [0 .. 32768) Whh-tail (first 24576 floats) then reused for Wt;
//           [32768 .. 36864) zx.
// =========================================================================
__global__ void __launch_bounds__(512) k_lstm(
    const float* __restrict__ Whh, const float* __restrict__ Wt,
    const float* __restrict__ btv, const float* __restrict__ vt,
    const float* __restrict__ Wcls, const float* __restrict__ bcls,
    float* __restrict__ out)
{
    extern __shared__ float dynl[];
    float* sWtail = dynl;                 // [KTAIL][512], later Wt[128][256]
    float* szx    = dynl + 32768;         // [8][512]
    __shared__ __align__(16) float sh[128];
    __shared__ float sg[512];
    __shared__ float shs[8 * 128];
    __shared__ float sU8[8], sRedT[8][8], sRedF[4];

    int b = blockIdx.x, tid = threadIdx.x;
    int warp = tid >> 5, lane = tid & 31;

    // ---- preload Whh columns: 80 rows into registers ----
    float w[KREG];
    #pragma unroll
    for (int k = 0; k < KREG; ++k) w[k] = Whh[k * 512 + tid];

    // tail rows 80..127 into smem ( [KTAIL][512] row-major )
    {
        const float4* src = reinterpret_cast<const float4*>(Whh + KREG * 512);
        float4* dst = reinterpret_cast<float4*>(sWtail);
        #pragma unroll
        for (int i = 0; i < KTAIL * 128 / 512; ++i)  // 12
            dst[tid + 512 * i] = src[tid + 512 * i];
    }
    // zx
    {
        const float4* src = reinterpret_cast<const float4*>(d_zx + b * 4096);
        float4* dst = reinterpret_cast<float4*>(szx);
        dst[tid] = src[tid];
        dst[tid + 512] = src[tid + 512];
    }
    if (tid < 128) sh[tid] = 0.f;
    float cstate = 0.f;
    __syncthreads();

    // ---- recurrence ----
    for (int t = 0; t < 8; ++t) {
        float z = szx[t * 512 + tid];
        if (t > 0) {
            float a0 = 0.f, a1 = 0.f, a2 = 0.f, a3 = 0.f;
            #pragma unroll
            for (int k4 = 0; k4 < KREG / 4; ++k4) {
                float4 hv = *reinterpret_cast<const float4*>(&sh[k4 * 4]);
                a0 += hv.x * w[k4 * 4 + 0];
                a1 += hv.y * w[k4 * 4 + 1];
                a2 += hv.z * w[k4 * 4 + 2];
                a3 += hv.w * w[k4 * 4 + 3];
            }
            #pragma unroll
            for (int kk = 0; kk < KTAIL; kk += 4) {
                float4 hv = *reinterpret_cast<const float4*>(&sh[KREG + kk]);
                a0 += hv.x * sWtail[(kk + 0) * 512 + tid];
                a1 += hv.y * sWtail[(kk + 1) * 512 + tid];
                a2 += hv.z * sWtail[(kk + 2) * 512 + tid];
                a3 += hv.w * sWtail[(kk + 3) * 512 + tid];
            }
            z += (a0 + a1) + (a2 + a3);
        }
        // activate: sigmoid for i,f,o; tanh for g (256 <= tid < 384)
        float a = (tid >= 256 && tid < 384) ? tanhf(z)
                                           : 1.f / (1.f + expf(-z));
        sg[tid] = a;
        __syncthreads();
        if (tid < 128) {
            float c = sg[tid + 128] * cstate + sg[tid] * sg[tid + 256];
            cstate = c;
            float h = sg[tid + 384] * tanhf(c);
            sh[tid] = h;
            shs[t * 128 + tid] = h;
        }
        __syncthreads();
    }

    // ---- load Wt into dyn smem (overwrites Whh tail) ----
    {
        const float4* src = reinterpret_cast<const float4*>(Wt);
        float4* dst = reinterpret_cast<float4*>(sWtail);
        #pragma unroll
        for (int i = 0; i < 16; ++i)
            dst[tid + 512 * i] = src[tid + 512 * i];
    }
    __syncthreads();

    // ---- temporal attention: tasks (t, ta), 4 reps of 512 ----
    #pragma unroll
    for (int rep = 0; rep < 4; ++rep) {
        int task = rep * 512 + tid;
        int t = task >> 8;
        int ta = task & 255;
        float a = btv[ta];
        #pragma unroll 8
        for (int h = 0; h < 128; ++h) a += shs[t * 128 + h] * sWtail[h * TAd + ta];
        a = tanhf(a) * vt[ta];
        #pragma unroll
        for (int o = 16; o > 0; o >>= 1) a += __shfl_xor_sync(0xffffffffu, a, o);
        if (lane == 0) sRedT[t][warp & 7] = a;
    }
    __syncthreads();
    if (tid < 8) {
        float sum = 0.f;
        #pragma unroll
        for (int ww = 0; ww < 8; ++ww) sum += sRedT[tid][ww];
        sU8[tid] = sum;
    }
    __syncthreads();
    if (tid == 0) {
        float mx = -3.0e38f;
        #pragma unroll
        for (int t = 0; t < 8; ++t) mx = fmaxf(mx, sU8[t]);
        float se = 0.f;
        #pragma unroll
        for (int t = 0; t < 8; ++t) { float e = expf(sU8[t] - mx); sU8[t] = e; se += e; }
        float inv = 1.f / se;
        #pragma unroll
        for (int t = 0; t < 8; ++t) sU8[t] *= inv;
    }
    __syncthreads();

    float partial = 0.f;
    if (tid < 128) {
        float p = 0.f;
        #pragma unroll
        for (int t = 0; t < 8; ++t) p += sU8[t] * shs[t * 128 + tid];
        partial = p * Wcls[tid];
    }
    #pragma unroll
    for (int o = 16; o > 0; o >>= 1) partial += __shfl_xor_sync(0xffffffffu, partial, o);
    if (lane == 0 && warp < 4) sRedF[warp] = partial;
    __syncthreads();
    if (tid == 0) out[b] = sRedF[0] + sRedF[1] + sRedF[2] + sRedF[3] + bcls[0];
}

// =========================================================================
extern "C" void kernel_launch(void* const* d_in, const int* in_sizes, int n_in,
                              void* d_out, int out_size)
{
    const float* code_x = (const float*)d_in[0];
    const float* prior  = (const float*)d_in[4];
    const float* adj    = (const float*)d_in[5];
    const float* c_emb  = (const float*)d_in[6];
    const float* W1     = (const float*)d_in[7];
    const float* b1     = (const float*)d_in[8];
    const float* W2     = (const float*)d_in[9];
    const float* b2     = (const float*)d_in[10];
    const float* Wp     = (const float*)d_in[11];
    const float* bp     = (const float*)d_in[12];
    const float* ln_g   = (const float*)d_in[13];
    const float* ln_b   = (const float*)d_in[14];
    const float* Wc     = (const float*)d_in[15];
    const float* bc     = (const float*)d_in[16];
    const float* vc     = (const float*)d_in[17];
    const float* Wt     = (const float*)d_in[18];
    const float* btv    = (const float*)d_in[19];
    const float* vt     = (const float*)d_in[20];
    const float* Wih    = (const float*)d_in[21];
    const float* Whh    = (const float*)d_in[22];
    const float* bih    = (const float*)d_in[23];
    const float* bhh    = (const float*)d_in[24];
    const float* Wcls   = (const float*)d_in[25];
    const float* bcls   = (const float*)d_in[26];

    const int AC_SMEM = (128 * UTS + ROWS * Gd + 128 * UTS) * (int)sizeof(float);
    const int D_SMEM  = SMAX * Gd * (int)sizeof(float);
    const int L_SMEM  = (32768 + 8 * 512) * (int)sizeof(float);

    cudaFuncSetAttribute(kAC, cudaFuncAttributeMaxDynamicSharedMemorySize, AC_SMEM);
    cudaFuncSetAttribute(kD, cudaFuncAttributeMaxDynamicSharedMemorySize, D_SMEM);
    cudaFuncSetAttribute(k_lstm, cudaFuncAttributeMaxDynamicSharedMemorySize, L_SMEM);

    k_setup<<<NCODE + 1 + BT, 128>>>(adj, code_x, prior, c_emb, W1);
    kAC<<<dim3(3, BT), 512, AC_SMEM>>>(
        prior, b1, W2, b2, Wp, bp, ln_g, ln_b, Wc, bc, vc);
    kD<<<BT, 512, D_SMEM>>>(Wih, bih, bhh);
    k_lstm<<<NB, 512, L_SMEM>>>(Whh, Wt, btv, vt, Wcls, bcls, (float*)d_out);
}

// round 5
// speedup vs baseline: 2.4332x; 1.0557x over previous
#include <cuda_runtime.h>
#include <math.h>

// Problem constants
#define NB 8
#define NT 8
#define BT 64
#define NCODE 1024
#define Gd 128
#define CSd 64
#define TAd 256
#define SMAX 96
#define CMAX 64
#define ROWS 32          // rows per kAC block
#define UTS 36           // padded transposed stride (floats, mult of 4)
#define KREG 80          // Whh rows held in registers in k_lstm
#define KTAIL 48         // Whh rows held in smem in k_lstm

// ---------------- fast activations (inf-safe) ----------------
__device__ __forceinline__ float fsig(float x) {
    return 1.f / (1.f + __expf(-x));
}
__device__ __forceinline__ float ftanh(float x) {
    return 1.f - 2.f / (__expf(2.f * x) + 1.f);
}

// ---------------- device scratch ----------------
__device__ float d_EW1[NCODE * Gd];
__device__ float2 d_csr[NCODE * CMAX];
__device__ int    d_ccnt[NCODE];
__device__ int    d_act[BT * SMAX];
__device__ int    d_scnt[BT];
__device__ unsigned char d_rank[BT * NCODE];
__device__ float  d_psum;
__device__ float  d_logit[BT * SMAX];
__device__ float  d_co[BT * SMAX * Gd];
__device__ float  d_zx[BT * 512];

// =========================================================================
// K1: setup — EW1, adj CSR (2-pass MLP scan), active lists, prior sum
// =========================================================================
__global__ void __launch_bounds__(128) k_setup(
    const float* __restrict__ adj, const float* __restrict__ code_x,
    const float* __restrict__ prior, const float* __restrict__ c_emb,
    const float* __restrict__ W1)
{
    int blk = blockIdx.x;
    int tid = threadIdx.x;
    int warp = tid >> 5, lane = tid & 31;

    if (blk < NCODE) {
        int n = blk;
        __shared__ float sc[CSd];
        __shared__ int wcnt[4];
        if (tid < CSd) sc[tid] = c_emb[n * CSd + tid];
        __syncthreads();
        float acc = 0.f;
        #pragma unroll 16
        for (int j = 0; j < CSd; ++j) acc += sc[j] * W1[j * Gd + tid];
        d_EW1[n * Gd + tid] = acc;

        float vals[8];
        int myoff[8];
        int cnt = 0;
        #pragma unroll
        for (int it = 0; it < 8; ++it)
            vals[it] = adj[n * NCODE + warp * 256 + it * 32 + lane];
        #pragma unroll
        for (int it = 0; it < 8; ++it) {
            unsigned m = __ballot_sync(0xffffffffu, vals[it] != 0.f);
            myoff[it] = cnt + __popc(m & ((1u << lane) - 1u));
            cnt += __popc(m);
        }
        if (lane == 0) wcnt[warp] = cnt;
        __syncthreads();
        int base = 0;
        for (int w = 0; w < warp; ++w) base += wcnt[w];
        #pragma unroll
        for (int it = 0; it < 8; ++it) {
            if (vals[it] != 0.f) {
                int pos = base + myoff[it];
                if (pos < CMAX)
                    d_csr[n * CMAX + pos] =
                        make_float2(__int_as_float(warp * 256 + it * 32 + lane), vals[it]);
            }
        }
        if (tid == 0) d_ccnt[n] = min(wcnt[0] + wcnt[1] + wcnt[2] + wcnt[3], CMAX);
    } else if (blk == NCODE) {
        __shared__ float sr[128];
        float s = 0.f;
        for (int i = tid; i < NCODE; i += 128) s += prior[i];
        sr[tid] = s; __syncthreads();
        for (int o = 64; o > 0; o >>= 1) {
            if (tid < o) sr[tid] += sr[tid + o];
            __syncthreads();
        }
        if (tid == 0) d_psum = sr[0];
    } else {
        int bt = blk - (NCODE + 1);
        __shared__ int wcnt2[4];
        for (int i = tid; i < NCODE; i += 128) d_rank[bt * NCODE + i] = 0xFF;
        __syncthreads();
        float vals[8];
        int myoff[8];
        int cnt = 0;
        #pragma unroll
        for (int it = 0; it < 8; ++it)
            vals[it] = code_x[bt * NCODE + warp * 256 + it * 32 + lane];
        #pragma unroll
        for (int it = 0; it < 8; ++it) {
            unsigned m = __ballot_sync(0xffffffffu, vals[it] != 0.f);
            myoff[it] = cnt + __popc(m & ((1u << lane) - 1u));
            cnt += __popc(m);
        }
        if (lane == 0) wcnt2[warp] = cnt;
        __syncthreads();
        int base = 0;
        for (int w = 0; w < warp; ++w) base += wcnt2[w];
        #pragma unroll
        for (int it = 0; it < 8; ++it) {
            if (vals[it] != 0.f) {
                int pos = base + myoff[it];
                int idx = warp * 256 + it * 32 + lane;
                if (pos < SMAX) {
                    d_act[bt * SMAX + pos] = idx;
                    d_rank[bt * NCODE + idx] = (unsigned char)pos;
                }
            }
        }
        if (tid == 0)
            d_scnt[bt] = min(wcnt2[0] + wcnt2[1] + wcnt2[2] + wcnt2[3], SMAX);
    }
}

// =========================================================================
// K2: kAC — sparse GCN rows + co GEMM + LN residual + logits. grid (3,64)x512
// dyn smem layout: sUT[128][UTS] | sCo[32][128] | sCoT[128][UTS] | sEW1[96][128]
// =========================================================================
__global__ void __launch_bounds__(512) kAC(
    const float* __restrict__ prior, const float* __restrict__ b1,
    const float* __restrict__ W2,  const float* __restrict__ b2,
    const float* __restrict__ Wp,  const float* __restrict__ bp,
    const float* __restrict__ lng, const float* __restrict__ lnb,
    const float* __restrict__ Wc,  const float* __restrict__ bc,
    const float* __restrict__ vc)
{
    extern __shared__ float dyn[];
    float* sUT  = dyn;                       // [128][UTS]
    float* sCo  = dyn + 128 * UTS;           // [32][128]
    float* sCoT = sCo + ROWS * Gd;           // [128][UTS]
    float* sEW1 = sCoT + 128 * UTS;          // [96][128] indexed by rank
    __shared__ unsigned char sRank[NCODE];
    __shared__ unsigned char sCcnt[NCODE];
    __shared__ float sPr[ROWS];
    __shared__ float sRedC[4][4][8];
    __shared__ int sActAll[SMAX];

    int bt = blockIdx.y;
    int base = blockIdx.x * ROWS;
    int tid = threadIdx.x;
    int warp = tid >> 5, lane = tid & 31;
    int s = tid >> 7, g = tid & 127;
    int wis = warp & 3;
    int S = d_scnt[bt];
    int rows = min(S - base, ROWS);
    if (rows <= 0) return;

    for (int i = tid; i < NCODE; i += 512) {
        sRank[i] = d_rank[bt * NCODE + i];
        sCcnt[i] = (unsigned char)d_ccnt[i];
    }
    if (tid < SMAX) sActAll[tid] = (tid < S) ? d_act[bt * SMAX + tid] : 0;
    if (tid < ROWS)
        sPr[tid] = (tid < rows) ? prior[d_act[bt * SMAX + base + tid]] / d_psum : 0.f;
    __syncthreads();

    // ---- stage active EW1 rows (rank-indexed) ----
    for (int idx = tid; idx < S * Gd; idx += 512) {
        int r = idx >> 7;
        sEW1[idx] = d_EW1[sActAll[r] * Gd + (idx & 127)];
    }
    __syncthreads();

    // ---- Phase A: u rows -> transposed smem (EW1+ccnt from smem) ----
    {
        float bb[4];
        #pragma unroll
        for (int q = 0; q < 4; ++q) bb[q] = b1[lane + 32 * q];
        for (int mi = warp; mi < ROWS; mi += 16) {
            if (mi < rows) {
                int am = sActAll[base + mi];
                float acc[4] = {0.f, 0.f, 0.f, 0.f};
                int cm = sCcnt[am];
                const float2* rowm = d_csr + am * CMAX;
                for (int e = 0; e < cm; ++e) {
                    float2 cv = rowm[e];
                    int n = __float_as_int(cv.x);
                    float v = cv.y;
                    float hv[4];
                    #pragma unroll
                    for (int q = 0; q < 4; ++q) hv[q] = bb[q];
                    int cn = sCcnt[n];
                    const float2* rown = d_csr + n * CMAX;
                    int e2 = 0;
                    for (; e2 + 4 <= cn; e2 += 4) {
                        float2 c0 = rown[e2], c1 = rown[e2 + 1],
                               c2 = rown[e2 + 2], c3 = rown[e2 + 3];
                        unsigned char r0 = sRank[__float_as_int(c0.x)];
                        unsigned char r1 = sRank[__float_as_int(c1.x)];
                        unsigned char r2 = sRank[__float_as_int(c2.x)];
                        unsigned char r3 = sRank[__float_as_int(c3.x)];
                        if (r0 != 0xFF) {
                            const float* ew = sEW1 + (int)r0 * Gd;
                            #pragma unroll
                            for (int q = 0; q < 4; ++q) hv[q] += c0.y * ew[lane + 32 * q];
                        }
                        if (r1 != 0xFF) {
                            const float* ew = sEW1 + (int)r1 * Gd;
                            #pragma unroll
                            for (int q = 0; q < 4; ++q) hv[q] += c1.y * ew[lane + 32 * q];
                        }
                        if (r2 != 0xFF) {
                            const float* ew = sEW1 + (int)r2 * Gd;
                            #pragma unroll
                            for (int q = 0; q < 4; ++q) hv[q] += c2.y * ew[lane + 32 * q];
                        }
                        if (r3 != 0xFF) {
                            const float* ew = sEW1 + (int)r3 * Gd;
                            #pragma unroll
                            for (int q = 0; q < 4; ++q) hv[q] += c3.y * ew[lane + 32 * q];
                        }
                    }
                    for (; e2 < cn; ++e2) {
                        float2 c0 = rown[e2];
                        unsigned char r0 = sRank[__float_as_int(c0.x)];
                        if (r0 != 0xFF) {
                            const float* ew = sEW1 + (int)r0 * Gd;
                            #pragma unroll
                            for (int q = 0; q < 4; ++q) hv[q] += c0.y * ew[lane + 32 * q];
                        }
                    }
                    #pragma unroll
                    for (int q = 0; q < 4; ++q) acc[q] += v * fmaxf(hv[q], 0.f);
                }
                #pragma unroll
                for (int q = 0; q < 4; ++q)
                    sUT[(lane + 32 * q) * UTS + mi] = acc[q];
            } else {
                #pragma unroll
                for (int q = 0; q < 4; ++q) {
                    sUT[(lane + 32 * q) * UTS + mi] = 0.f;
                    sCoT[(lane + 32 * q) * UTS + mi] = 0.f;
                }
            }
        }
    }
    __syncthreads();

    // ---- Phase B: co = u @ W2 + b2 ----
    {
        float acc[8];
        #pragma unroll
        for (int i = 0; i < 8; ++i) acc[i] = 0.f;
        #pragma unroll 4
        for (int j = 0; j < Gd; ++j) {
            float w = W2[j * Gd + g];
            float4 u0 = *reinterpret_cast<const float4*>(&sUT[j * UTS + s * 8]);
            float4 u1 = *reinterpret_cast<const float4*>(&sUT[j * UTS + s * 8 + 4]);
            acc[0] += u0.x * w; acc[1] += u0.y * w; acc[2] += u0.z * w; acc[3] += u0.w * w;
            acc[4] += u1.x * w; acc[5] += u1.y * w; acc[6] += u1.z * w; acc[7] += u1.w * w;
        }
        float b2g = b2[g];
        #pragma unroll
        for (int i = 0; i < 8; ++i)
            sCo[(s * 8 + i) * Gd + g] = acc[i] + b2g;
    }
    __syncthreads();

    // ---- Phase C: prior modulation + LN + leaky relu residual ----
    {
        float wpv[4], bpv[4], lg[4], lb[4];
        #pragma unroll
        for (int q = 0; q < 4; ++q) {
            int gg = lane + 32 * q;
            wpv[q] = Wp[gg]; bpv[q] = bp[gg]; lg[q] = lng[gg]; lb[q] = lnb[gg];
        }
        for (int mi = warp; mi < rows; mi += 16) {
            float p = sPr[mi];
            float co[4], cw[4];
            float sum = 0.f;
            #pragma unroll
            for (int q = 0; q < 4; ++q) {
                co[q] = sCo[mi * Gd + lane + 32 * q];
                cw[q] = co[q] * (p * wpv[q] + bpv[q]);
                sum += cw[q];
            }
            #pragma unroll
            for (int o = 16; o > 0; o >>= 1) sum += __shfl_xor_sync(0xffffffffu, sum, o);
            float mu = sum * (1.f / 128.f);
            float vs = 0.f;
            #pragma unroll
            for (int q = 0; q < 4; ++q) { float d = cw[q] - mu; vs += d * d; }
            #pragma unroll
            for (int o = 16; o > 0; o >>= 1) vs += __shfl_xor_sync(0xffffffffu, vs, o);
            float inv = rsqrtf(vs * (1.f / 128.f) + 1e-5f);
            #pragma unroll
            for (int q = 0; q < 4; ++q) {
                float nv = (cw[q] - mu) * inv * lg[q] + lb[q];
                nv = (nv >= 0.f) ? nv : 0.01f * nv;
                float r = co[q] + nv;
                sCo[mi * Gd + lane + 32 * q] = r;
                sCoT[(lane + 32 * q) * UTS + mi] = r;
            }
        }
    }
    __syncthreads();

    // ---- Phase C2: logits = tanh(co@Wc + bc) @ vc ----
    {
        float acc[8];
        #pragma unroll
        for (int i = 0; i < 8; ++i) acc[i] = 0.f;
        #pragma unroll 4
        for (int j = 0; j < Gd; ++j) {
            float w = Wc[j * Gd + g];
            float4 u0 = *reinterpret_cast<const float4*>(&sCoT[j * UTS + s * 8]);
            float4 u1 = *reinterpret_cast<const float4*>(&sCoT[j * UTS + s * 8 + 4]);
            acc[0] += u0.x * w; acc[1] += u0.y * w; acc[2] += u0.z * w; acc[3] += u0.w * w;
            acc[4] += u1.x * w; acc[5] += u1.y * w; acc[6] += u1.z * w; acc[7] += u1.w * w;
        }
        float bcg = bc[g], vcg = vc[g];
        #pragma unroll
        for (int i = 0; i < 8; ++i) {
            float tv = ftanh(acc[i] + bcg) * vcg;
            #pragma unroll
            for (int o = 16; o > 0; o >>= 1)
                tv += __shfl_xor_sync(0xffffffffu, tv, o);
            if (lane == 0) sRedC[s][wis][i] = tv;
        }
        __syncthreads();
        if (tid < 32) {
            int s2 = tid >> 3, i2 = tid & 7;
            int row = s2 * 8 + i2;
            if (row < rows)
                d_logit[bt * SMAX + base + row] =
                    sRedC[s2][0][i2] + sRedC[s2][1][i2] +
                    sRedC[s2][2][i2] + sRedC[s2][3][i2];
        }
    }

    for (int idx = tid; idx < rows * Gd; idx += 512)
        d_co[(bt * SMAX + base) * Gd + idx] = sCo[idx];
}

// =========================================================================
// K3: kD — softmax, visit, zx. grid 64 x 512
// =========================================================================
__global__ void __launch_bounds__(512) kD(
    const float* __restrict__ Wih, const float* __restrict__ bih,
    const float* __restrict__ bhh)
{
    extern __shared__ float sCoD[];
    __shared__ float sAttn[SMAX];
    __shared__ float sVis[Gd];
    __shared__ float sVp[4][Gd];

    int bt = blockIdx.x, tid = threadIdx.x;
    int S = d_scnt[bt];
    int grp = tid >> 7, g = tid & 127;

    for (int idx = tid; idx < S * Gd; idx += 512)
        sCoD[idx] = d_co[bt * SMAX * Gd + idx];

    if (tid < 32) {
        float mx = -3.0e38f;
        for (int m = tid; m < S; m += 32) {
            float l = d_logit[bt * SMAX + m];
            sAttn[m] = l;
            mx = fmaxf(mx, l);
        }
        #pragma unroll
        for (int o = 16; o > 0; o >>= 1)
            mx = fmaxf(mx, __shfl_xor_sync(0xffffffffu, mx, o));
        float se = 0.f;
        for (int m = tid; m < S; m += 32) {
            float e = __expf(sAttn[m] - mx);
            sAttn[m] = e; se += e;
        }
        #pragma unroll
        for (int o = 16; o > 0; o >>= 1) se += __shfl_xor_sync(0xffffffffu, se, o);
        float inv = 1.f / se;
        for (int m = tid; m < S; m += 32) sAttn[m] *= inv;
    }
    __syncthreads();

    {
        float v = 0.f;
        for (int m = grp; m < S; m += 4) v += sAttn[m] * sCoD[m * Gd + g];
        sVp[grp][g] = v;
    }
    __syncthreads();
    if (tid < Gd)
        sVis[tid] = sVp[0][tid] + sVp[1][tid] + sVp[2][tid] + sVp[3][tid];
    __syncthreads();

    {
        int j = tid;
        float z = bih[j] + bhh[j];
        #pragma unroll 8
        for (int k = 0; k < Gd; ++k) z += sVis[k] * Wih[k * 512 + j];
        d_zx[bt * 512 + j] = z;
    }
}

// =========================================================================
// K4: LSTM + temporal attention + classifier. grid 8 x 512.
// =========================================================================
__global__ void __launch_bounds__(512) k_lstm(
    const float* __restrict__ Whh, const float* __restrict__ Wt,
    const float* __restrict__ btv, const float* __restrict__ vt,
    const float* __restrict__ Wcls, const float* __restrict__ bcls,
    float* __restrict__ out)
{
    extern __shared__ float dynl[];
    float* sWtail = dynl;                 // [KTAIL][512], later Wt[128][256]
    float* szx    = dynl + 32768;         // [8][512]
    __shared__ __align__(16) float sh[128];
    __shared__ float sg[512];
    __shared__ float shs[8 * 128];
    __shared__ float sU8[8], sRedT[8][8], sRedF[4];

    int b = blockIdx.x, tid = threadIdx.x;
    int warp = tid >> 5, lane = tid & 31;

    float w[KREG];
    #pragma unroll
    for (int k = 0; k < KREG; ++k) w[k] = Whh[k * 512 + tid];

    {
        const float4* src = reinterpret_cast<const float4*>(Whh + KREG * 512);
        float4* dst = reinterpret_cast<float4*>(sWtail);
        #pragma unroll
        for (int i = 0; i < KTAIL * 128 / 512; ++i)
            dst[tid + 512 * i] = src[tid + 512 * i];
    }
    {
        const float4* src = reinterpret_cast<const float4*>(d_zx + b * 4096);
        float4* dst = reinterpret_cast<float4*>(szx);
        dst[tid] = src[tid];
        dst[tid + 512] = src[tid + 512];
    }
    if (tid < 128) sh[tid] = 0.f;
    float cstate = 0.f;
    __syncthreads();

    for (int t = 0; t < 8; ++t) {
        float z = szx[t * 512 + tid];
        if (t > 0) {
            float a0 = 0.f, a1 = 0.f, a2 = 0.f, a3 = 0.f;
            #pragma unroll
            for (int k4 = 0; k4 < KREG / 4; ++k4) {
                float4 hv = *reinterpret_cast<const float4*>(&sh[k4 * 4]);
                a0 += hv.x * w[k4 * 4 + 0];
                a1 += hv.y * w[k4 * 4 + 1];
                a2 += hv.z * w[k4 * 4 + 2];
                a3 += hv.w * w[k4 * 4 + 3];
            }
            #pragma unroll
            for (int kk = 0; kk < KTAIL; kk += 4) {
                float4 hv = *reinterpret_cast<const float4*>(&sh[KREG + kk]);
                a0 += hv.x * sWtail[(kk + 0) * 512 + tid];
                a1 += hv.y * sWtail[(kk + 1) * 512 + tid];
                a2 += hv.z * sWtail[(kk + 2) * 512 + tid];
                a3 += hv.w * sWtail[(kk + 3) * 512 + tid];
            }
            z += (a0 + a1) + (a2 + a3);
        }
        float a = (tid >= 256 && tid < 384) ? ftanh(z) : fsig(z);
        sg[tid] = a;
        __syncthreads();
        if (tid < 128) {
            float c = sg[tid + 128] * cstate + sg[tid] * sg[tid + 256];
            cstate = c;
            float h = sg[tid + 384] * ftanh(c);
            sh[tid] = h;
            shs[t * 128 + tid] = h;
        }
        __syncthreads();
    }

    {
        const float4* src = reinterpret_cast<const float4*>(Wt);
        float4* dst = reinterpret_cast<float4*>(sWtail);
        #pragma unroll
        for (int i = 0; i < 16; ++i)
            dst[tid + 512 * i] = src[tid + 512 * i];
    }
    __syncthreads();

    #pragma unroll
    for (int rep = 0; rep < 4; ++rep) {
        int task = rep * 512 + tid;
        int t = task >> 8;
        int ta = task & 255;
        float a = btv[ta];
        #pragma unroll 8
        for (int h = 0; h < 128; ++h) a += shs[t * 128 + h] * sWtail[h * TAd + ta];
        a = ftanh(a) * vt[ta];
        #pragma unroll
        for (int o = 16; o > 0; o >>= 1) a += __shfl_xor_sync(0xffffffffu, a, o);
        if (lane == 0) sRedT[t][warp & 7] = a;
    }
    __syncthreads();
    if (tid < 8) {
        float sum = 0.f;
        #pragma unroll
        for (int ww = 0; ww < 8; ++ww) sum += sRedT[tid][ww];
        sU8[tid] = sum;
    }
    __syncthreads();
    if (tid == 0) {
        float mx = -3.0e38f;
        #pragma unroll
        for (int t = 0; t < 8; ++t) mx = fmaxf(mx, sU8[t]);
        float se = 0.f;
        #pragma unroll
        for (int t = 0; t < 8; ++t) { float e = __expf(sU8[t] - mx); sU8[t] = e; se += e; }
        float inv = 1.f / se;
        #pragma unroll
        for (int t = 0; t < 8; ++t) sU8[t] *= inv;
    }
    __syncthreads();

    float partial = 0.f;
    if (tid < 128) {
        float p = 0.f;
        #pragma unroll
        for (int t = 0; t < 8; ++t) p += sU8[t] * shs[t * 128 + tid];
        partial = p * Wcls[tid];
    }
    #pragma unroll
    for (int o = 16; o > 0; o >>= 1) partial += __shfl_xor_sync(0xffffffffu, partial, o);
    if (lane == 0 && warp < 4) sRedF[warp] = partial;
    __syncthreads();
    if (tid == 0) out[b] = sRedF[0] + sRedF[1] + sRedF[2] + sRedF[3] + bcls[0];
}

// =========================================================================
extern "C" void kernel_launch(void* const* d_in, const int* in_sizes, int n_in,
                              void* d_out, int out_size)
{
    const float* code_x = (const float*)d_in[0];
    const float* prior  = (const float*)d_in[4];
    const float* adj    = (const float*)d_in[5];
    const float* c_emb  = (const float*)d_in[6];
    const float* W1     = (const float*)d_in[7];
    const float* b1     = (const float*)d_in[8];
    const float* W2     = (const float*)d_in[9];
    const float* b2     = (const float*)d_in[10];
    const float* Wp     = (const float*)d_in[11];
    const float* bp     = (const float*)d_in[12];
    const float* ln_g   = (const float*)d_in[13];
    const float* ln_b   = (const float*)d_in[14];
    const float* Wc     = (const float*)d_in[15];
    const float* bc     = (const float*)d_in[16];
    const float* vc     = (const float*)d_in[17];
    const float* Wt     = (const float*)d_in[18];
    const float* btv    = (const float*)d_in[19];
    const float* vt     = (const float*)d_in[20];
    const float* Wih    = (const float*)d_in[21];
    const float* Whh    = (const float*)d_in[22];
    const float* bih    = (const float*)d_in[23];
    const float* bhh    = (const float*)d_in[24];
    const float* Wcls   = (const float*)d_in[25];
    const float* bcls   = (const float*)d_in[26];

    const int AC_SMEM = (2 * 128 * UTS + ROWS * Gd + SMAX * Gd) * (int)sizeof(float);
    const int D_SMEM  = SMAX * Gd * (int)sizeof(float);
    const int L_SMEM  = (32768 + 8 * 512) * (int)sizeof(float);

    cudaFuncSetAttribute(kAC, cudaFuncAttributeMaxDynamicSharedMemorySize, AC_SMEM);
    cudaFuncSetAttribute(kD, cudaFuncAttributeMaxDynamicSharedMemorySize, D_SMEM);
    cudaFuncSetAttribute(k_lstm, cudaFuncAttributeMaxDynamicSharedMemorySize, L_SMEM);

    k_setup<<<NCODE + 1 + BT, 128>>>(adj, code_x, prior, c_emb, W1);
    kAC<<<dim3(3, BT), 512, AC_SMEM>>>(
        prior, b1, W2, b2, Wp, bp, ln_g, ln_b, Wc, bc, vc);
    kD<<<BT, 512, D_SMEM>>>(Wih, bih, bhh);
    k_lstm<<<NB, 512, L_SMEM>>>(Whh, Wt, btv, vt, Wcls, bcls, (float*)d_out);
}